// round 2
// baseline (speedup 1.0000x reference)
#include <cuda_runtime.h>
#include <cstddef>

#define BM 128
#define BN 128
#define BK 16
#define TM 8
#define TN 8

// Scratch (no allocations allowed): 3 x 64 MiB device globals (.bss, not in cubin)
__device__ float g_h  [32u * 1024u * 512u];
__device__ float g_agg[32u * 1024u * 512u];
__device__ float g_h2 [32u * 1024u * 512u];

// C[M,N] = act( [A1 | A2] @ W + bias )
// A1: M x K1 row-major, A2: M x K2 row-major (concat along K), W: (K1+K2) x N row-major.
// Batched via blockIdx.z with strides sA (A1), sW, sC. act: 0=none, 1=relu, 2=prelu(alpha per col)
__global__ __launch_bounds__(256, 2)
void sgemm_kernel(const float* __restrict__ A1, int K1,
                  const float* __restrict__ A2, int K2,
                  const float* __restrict__ Wm,
                  const float* __restrict__ bias,
                  float* __restrict__ C,
                  int M, int N,
                  long sA, long sW, long sC,
                  int act, const float* __restrict__ alpha)
{
    const int K = K1 + K2;
    const int bz = blockIdx.z;
    const float* A1b = A1 + (size_t)bz * sA;
    const float* A2b = A2;                       // only used when batch == 1
    const float* Wb  = Wm + (size_t)bz * sW;
    float*       Cb  = C  + (size_t)bz * sC;

    __shared__ float As[2][BK][BM];
    __shared__ float Bs[2][BK][BN];

    const int tid = threadIdx.x;
    const int tx  = tid & 15;   // N dir (16)
    const int ty  = tid >> 4;   // M dir (16)

    const int rowBase = blockIdx.y * BM;
    const int colBase = blockIdx.x * BN;

    float acc[TM][TN];
#pragma unroll
    for (int i = 0; i < TM; i++)
#pragma unroll
        for (int j = 0; j < TN; j++) acc[i][j] = 0.f;

    float4 aReg[2], bReg[2];

    auto fetch = [&](int kt) {
        const int kb = kt * BK;
        const float* Ap; int lda; int kOff;
        if (kb < K1) { Ap = A1b; lda = K1; kOff = kb; }
        else         { Ap = A2b; lda = K2; kOff = kb - K1; }
#pragma unroll
        for (int i = 0; i < 2; i++) {
            int f  = tid + (i << 8);
            int r  = f >> 2;
            int c4 = (f & 3) << 2;
            aReg[i] = *reinterpret_cast<const float4*>(Ap + (size_t)(rowBase + r) * lda + kOff + c4);
        }
#pragma unroll
        for (int i = 0; i < 2; i++) {
            int f  = tid + (i << 8);
            int r  = f >> 5;
            int c4 = (f & 31) << 2;
            bReg[i] = *reinterpret_cast<const float4*>(Wb + (size_t)(kb + r) * N + colBase + c4);
        }
    };

    auto stage = [&](int buf) {
#pragma unroll
        for (int i = 0; i < 2; i++) {
            int f  = tid + (i << 8);
            int r  = f >> 2;
            int c4 = (f & 3) << 2;
            As[buf][c4 + 0][r] = aReg[i].x;
            As[buf][c4 + 1][r] = aReg[i].y;
            As[buf][c4 + 2][r] = aReg[i].z;
            As[buf][c4 + 3][r] = aReg[i].w;
        }
#pragma unroll
        for (int i = 0; i < 2; i++) {
            int f  = tid + (i << 8);
            int r  = f >> 5;
            int c4 = (f & 31) << 2;
            *reinterpret_cast<float4*>(&Bs[buf][r][c4]) = bReg[i];
        }
    };

    fetch(0);
    stage(0);
    __syncthreads();

    const int nk = K / BK;
    for (int kt = 0; kt < nk; ++kt) {
        const int buf = kt & 1;
        if (kt + 1 < nk) fetch(kt + 1);

#pragma unroll
        for (int k = 0; k < BK; k++) {
            float4 a0 = *reinterpret_cast<const float4*>(&As[buf][k][ty * TM]);
            float4 a1 = *reinterpret_cast<const float4*>(&As[buf][k][ty * TM + 4]);
            float4 b0 = *reinterpret_cast<const float4*>(&Bs[buf][k][tx * TN]);
            float4 b1 = *reinterpret_cast<const float4*>(&Bs[buf][k][tx * TN + 4]);
            float a[TM] = {a0.x, a0.y, a0.z, a0.w, a1.x, a1.y, a1.z, a1.w};
            float b[TN] = {b0.x, b0.y, b0.z, b0.w, b1.x, b1.y, b1.z, b1.w};
#pragma unroll
            for (int i = 0; i < TM; i++)
#pragma unroll
                for (int j = 0; j < TN; j++)
                    acc[i][j] += a[i] * b[j];
        }

        if (kt + 1 < nk) stage(buf ^ 1);
        __syncthreads();
    }

    // Epilogue: bias + activation, vectorized store
#pragma unroll
    for (int i = 0; i < TM; i++) {
        const int r = rowBase + ty * TM + i;
#pragma unroll
        for (int j = 0; j < TN; j += 4) {
            const int c = colBase + tx * TN + j;
            float4 v = make_float4(acc[i][j], acc[i][j + 1], acc[i][j + 2], acc[i][j + 3]);
            if (bias) {
                v.x += bias[c + 0]; v.y += bias[c + 1];
                v.z += bias[c + 2]; v.w += bias[c + 3];
            }
            if (act == 1) {
                v.x = fmaxf(v.x, 0.f); v.y = fmaxf(v.y, 0.f);
                v.z = fmaxf(v.z, 0.f); v.w = fmaxf(v.w, 0.f);
            } else if (act == 2) {
                v.x = v.x > 0.f ? v.x : alpha[c + 0] * v.x;
                v.y = v.y > 0.f ? v.y : alpha[c + 1] * v.y;
                v.z = v.z > 0.f ? v.z : alpha[c + 2] * v.z;
                v.w = v.w > 0.f ? v.w : alpha[c + 3] * v.w;
            }
            *reinterpret_cast<float4*>(Cb + (size_t)r * N + c) = v;
        }
    }
}

// pred[M,2] = H[M,K] @ W[K,2] + b[2]   (warp per row)
__global__ void final_head_kernel(const float* __restrict__ H,
                                  const float* __restrict__ W,
                                  const float* __restrict__ b,
                                  float* __restrict__ out,
                                  int M, int K)
{
    __shared__ float w0[256], w1[256];
    const int tid = threadIdx.x;
    for (int i = tid; i < K; i += blockDim.x) {
        w0[i] = W[i * 2 + 0];
        w1[i] = W[i * 2 + 1];
    }
    __syncthreads();

    const int warp = tid >> 5;
    const int lane = tid & 31;
    const int row  = blockIdx.x * (blockDim.x >> 5) + warp;
    if (row >= M) return;

    const float* h = H + (size_t)row * K;
    float s0 = 0.f, s1 = 0.f;
    for (int c = lane; c < K; c += 32) {
        float v = h[c];
        s0 += v * w0[c];
        s1 += v * w1[c];
    }
#pragma unroll
    for (int o = 16; o; o >>= 1) {
        s0 += __shfl_xor_sync(0xFFFFFFFFu, s0, o);
        s1 += __shfl_xor_sync(0xFFFFFFFFu, s1, o);
    }
    if (lane == 0) {
        out[row * 2 + 0] = s0 + b[0];
        out[row * 2 + 1] = s1 + b[1];
    }
}

extern "C" void kernel_launch(void* const* d_in, const int* in_sizes, int n_in,
                              void* d_out, int out_size)
{
    const float* x   = (const float*)d_in[0];
    const float* adj = (const float*)d_in[1];
    const float* W1  = (const float*)d_in[2];
    const float* b1  = (const float*)d_in[3];
    const float* W2  = (const float*)d_in[4];
    const float* b2  = (const float*)d_in[5];
    const float* W3  = (const float*)d_in[6];
    const float* b3  = (const float*)d_in[7];
    const float* W4  = (const float*)d_in[8];
    const float* b4  = (const float*)d_in[9];
    const float* cW1 = (const float*)d_in[10];
    const float* cb1 = (const float*)d_in[11];
    const float* alp = (const float*)d_in[12];
    const float* cW2 = (const float*)d_in[13];
    const float* cb2 = (const float*)d_in[14];
    float* out = (float*)d_out;

    float *gh = nullptr, *gagg = nullptr, *gh2 = nullptr;
    cudaGetSymbolAddress((void**)&gh,   g_h);
    cudaGetSymbolAddress((void**)&gagg, g_agg);
    cudaGetSymbolAddress((void**)&gh2,  g_h2);

    const int Bb = 32, Nn = 1024, D = 256, Hd = 512, Hh = 256;
    const int MB = Bb * Nn;  // 32768

    auto gemm = [&](const float* A1, int K1, const float* A2, int K2,
                    const float* W, const float* bias, float* C,
                    int M, int N, int batch, long sA, long sW, long sC,
                    int act, const float* alpha) {
        dim3 g(N / BN, M / BM, batch);
        sgemm_kernel<<<g, 256>>>(A1, K1, A2, K2, W, bias, C, M, N, sA, sW, sC, act, alpha);
    };

    // ---- Layer 1: agg = adj @ x ; h1 = relu([x|agg] W1 + b1) ----
    gemm(adj, Nn, nullptr, 0, x, nullptr, gagg, Nn, D, Bb,
         (long)Nn * Nn, (long)Nn * D, (long)Nn * D, 0, nullptr);
    gemm(x, D, gagg, D, W1, b1, gh, MB, Hd, 1, 0, 0, 0, 1, nullptr);

    // ---- Layer 2: agg = adj @ h1 ; h2 = relu([h1|agg] W2 + b2) ----
    gemm(adj, Nn, nullptr, 0, gh, nullptr, gagg, Nn, Hd, Bb,
         (long)Nn * Nn, (long)Nn * Hd, (long)Nn * Hd, 0, nullptr);
    gemm(gh, Hd, gagg, Hd, W2, b2, gh2, MB, Hd, 1, 0, 0, 0, 1, nullptr);

    // ---- Layer 3: agg = adj @ h2 ; h3 = relu([h2|agg] W3 + b3) ----
    gemm(adj, Nn, nullptr, 0, gh2, nullptr, gagg, Nn, Hd, Bb,
         (long)Nn * Nn, (long)Nn * Hd, (long)Nn * Hd, 0, nullptr);
    gemm(gh2, Hd, gagg, Hd, W3, b3, gh, MB, Hh, 1, 0, 0, 0, 1, nullptr);

    // ---- Layer 4: agg = adj @ h3 ; h4 = relu([h3|agg] W4 + b4) ----
    gemm(adj, Nn, nullptr, 0, gh, nullptr, gagg, Nn, Hh, Bb,
         (long)Nn * Nn, (long)Nn * Hh, (long)Nn * Hh, 0, nullptr);
    gemm(gh, Hh, gagg, Hh, W4, b4, gh2, MB, Hh, 1, 0, 0, 0, 1, nullptr);

    // ---- Classifier: c1 = prelu(h4 @ cW1 + cb1) ; pred = c1 @ cW2 + cb2 ----
    gemm(gh2, Hh, nullptr, 0, cW1, cb1, gh, MB, Hh, 1, 0, 0, 0, 2, alp);
    final_head_kernel<<<MB / 8, 256>>>(gh, cW2, cb2, out, MB, Hh);
}

// round 4
// speedup vs baseline: 1.4232x; 1.4232x over previous
#include <cuda_runtime.h>
#include <cstdint>
#include <cstddef>

#define BM 128
#define BN 128
#define BK 16

// smem float offsets (double buffered)
#define AH_OFF 0        // [2][128*20]
#define AL_OFF 5120
#define BH_OFF 10240    // [2][16*132]
#define BL_OFF 14464
#define SMEM_FLOATS 18688   // 74752 bytes
#define A_STRIDE 20
#define B_STRIDE 132

// Scratch (no allocations allowed): 3 x 64 MiB device globals
__device__ float g_h  [32u * 1024u * 512u];
__device__ float g_agg[32u * 1024u * 512u];
__device__ float g_h2 [32u * 1024u * 512u];

__device__ __forceinline__ uint32_t f2tf32(float x) {
    uint32_t u;
    asm("cvt.rna.tf32.f32 %0, %1;" : "=r"(u) : "f"(x));
    return u;
}

__device__ __forceinline__ void mma_tf32(float c[4], const uint32_t a[4],
                                         uint32_t b0, uint32_t b1) {
    asm volatile(
        "mma.sync.aligned.m16n8k8.row.col.f32.tf32.tf32.f32 "
        "{%0,%1,%2,%3}, {%4,%5,%6,%7}, {%8,%9}, {%0,%1,%2,%3};"
        : "+f"(c[0]), "+f"(c[1]), "+f"(c[2]), "+f"(c[3])
        : "r"(a[0]), "r"(a[1]), "r"(a[2]), "r"(a[3]), "r"(b0), "r"(b1));
}

// C[M,N] = act( [A1 | A2] @ W + bias ), 3xTF32 tensor-core path.
// A1: M x K1 row-major, A2: M x K2 row-major (concat along K), W: (K1+K2) x N row-major.
__global__ __launch_bounds__(256, 2)
void tgemm_kernel(const float* __restrict__ A1, int K1,
                  const float* __restrict__ A2, int K2,
                  const float* __restrict__ Wm,
                  const float* __restrict__ bias,
                  float* __restrict__ C,
                  int M, int N,
                  long sA, long sW, long sC,
                  int act, const float* __restrict__ alpha)
{
    extern __shared__ float smem[];
    const int K = K1 + K2;
    const int bz = blockIdx.z;
    const float* A1b = A1 + (size_t)bz * sA;
    const float* A2b = A2;
    const float* Wb  = Wm + (size_t)bz * sW;
    float*       Cb  = C  + (size_t)bz * sC;

    const int tid  = threadIdx.x;
    const int wid  = tid >> 5;
    const int lane = tid & 31;
    const int warpM = wid >> 1;      // 0..3  -> 32-row slab
    const int warpN = wid & 1;       // 0..1  -> 64-col slab
    const int lr = lane >> 2;        // 0..7
    const int lc = lane & 3;         // 0..3

    const int rowBase = blockIdx.y * BM;
    const int colBase = blockIdx.x * BN;

    float acc[2][8][4];
#pragma unroll
    for (int mi = 0; mi < 2; mi++)
#pragma unroll
        for (int ni = 0; ni < 8; ni++)
#pragma unroll
            for (int j = 0; j < 4; j++) acc[mi][ni][j] = 0.f;

    float4 aReg[2], bReg[2];

    auto fetch = [&](int kt) {
        const int kb = kt * BK;
        const float* Ap; int lda; int kOff;
        if (kb < K1) { Ap = A1b; lda = K1; kOff = kb; }
        else         { Ap = A2b; lda = K2; kOff = kb - K1; }
#pragma unroll
        for (int i = 0; i < 2; i++) {
            int idx = tid + (i << 8);
            int r   = idx >> 2;
            int c4  = (idx & 3) << 2;
            aReg[i] = *reinterpret_cast<const float4*>(Ap + (size_t)(rowBase + r) * lda + kOff + c4);
        }
#pragma unroll
        for (int i = 0; i < 2; i++) {
            int idx = tid + (i << 8);
            int r   = idx >> 5;
            int c4  = (idx & 31) << 2;
            bReg[i] = *reinterpret_cast<const float4*>(Wb + (size_t)(kb + r) * N + colBase + c4);
        }
    };

    auto stage = [&](int buf) {
        float* sAh = smem + AH_OFF + buf * 2560;
        float* sAl = smem + AL_OFF + buf * 2560;
        float* sBh = smem + BH_OFF + buf * 2112;
        float* sBl = smem + BL_OFF + buf * 2112;
#pragma unroll
        for (int i = 0; i < 2; i++) {
            int idx = tid + (i << 8);
            int r   = idx >> 2;
            int c4  = (idx & 3) << 2;
            float v[4] = {aReg[i].x, aReg[i].y, aReg[i].z, aReg[i].w};
            float4 hi, lo;
            float* hp = &hi.x; float* lp = &lo.x;
#pragma unroll
            for (int j = 0; j < 4; j++) {
                float h = __uint_as_float(f2tf32(v[j]));
                hp[j] = h;
                lp[j] = __uint_as_float(f2tf32(v[j] - h));
            }
            *reinterpret_cast<float4*>(sAh + r * A_STRIDE + c4) = hi;
            *reinterpret_cast<float4*>(sAl + r * A_STRIDE + c4) = lo;
        }
#pragma unroll
        for (int i = 0; i < 2; i++) {
            int idx = tid + (i << 8);
            int r   = idx >> 5;
            int c4  = (idx & 31) << 2;
            float v[4] = {bReg[i].x, bReg[i].y, bReg[i].z, bReg[i].w};
            float4 hi, lo;
            float* hp = &hi.x; float* lp = &lo.x;
#pragma unroll
            for (int j = 0; j < 4; j++) {
                float h = __uint_as_float(f2tf32(v[j]));
                hp[j] = h;
                lp[j] = __uint_as_float(f2tf32(v[j] - h));
            }
            *reinterpret_cast<float4*>(sBh + r * B_STRIDE + c4) = hi;
            *reinterpret_cast<float4*>(sBl + r * B_STRIDE + c4) = lo;
        }
    };

    fetch(0);
    stage(0);
    __syncthreads();

    const int nk = K / BK;
    for (int kt = 0; kt < nk; ++kt) {
        const int buf = kt & 1;
        if (kt + 1 < nk) fetch(kt + 1);

        const float* sAh = smem + AH_OFF + buf * 2560;
        const float* sAl = smem + AL_OFF + buf * 2560;
        const float* sBh = smem + BH_OFF + buf * 2112;
        const float* sBl = smem + BL_OFF + buf * 2112;

#pragma unroll
        for (int ks = 0; ks < BK; ks += 8) {
            uint32_t ah[2][4], al[2][4];
#pragma unroll
            for (int mi = 0; mi < 2; mi++) {
                int m0 = warpM * 32 + mi * 16;
                int r0 = (m0 + lr) * A_STRIDE + ks + lc;
                int r1 = (m0 + 8 + lr) * A_STRIDE + ks + lc;
                ah[mi][0] = __float_as_uint(sAh[r0]);
                ah[mi][1] = __float_as_uint(sAh[r1]);
                ah[mi][2] = __float_as_uint(sAh[r0 + 4]);
                ah[mi][3] = __float_as_uint(sAh[r1 + 4]);
                al[mi][0] = __float_as_uint(sAl[r0]);
                al[mi][1] = __float_as_uint(sAl[r1]);
                al[mi][2] = __float_as_uint(sAl[r0 + 4]);
                al[mi][3] = __float_as_uint(sAl[r1 + 4]);
            }
#pragma unroll
            for (int ni = 0; ni < 8; ni++) {
                int n = warpN * 64 + ni * 8 + lr;
                int k0 = (ks + lc) * B_STRIDE + n;
                int k1 = (ks + 4 + lc) * B_STRIDE + n;
                uint32_t bh0 = __float_as_uint(sBh[k0]);
                uint32_t bh1 = __float_as_uint(sBh[k1]);
                uint32_t bl0 = __float_as_uint(sBl[k0]);
                uint32_t bl1 = __float_as_uint(sBl[k1]);
#pragma unroll
                for (int mi = 0; mi < 2; mi++) {
                    mma_tf32(acc[mi][ni], ah[mi], bh0, bh1);
                    mma_tf32(acc[mi][ni], al[mi], bh0, bh1);
                    mma_tf32(acc[mi][ni], ah[mi], bl0, bl1);
                }
            }
        }

        __syncthreads();
        if (kt + 1 < nk) {
            stage(buf ^ 1);
            __syncthreads();
        }
    }

    // Epilogue: bias + activation, float2 stores
#pragma unroll
    for (int mi = 0; mi < 2; mi++) {
#pragma unroll
        for (int ni = 0; ni < 8; ni++) {
#pragma unroll
            for (int half = 0; half < 2; half++) {
                int r = rowBase + warpM * 32 + mi * 16 + lr + half * 8;
                int c = colBase + warpN * 64 + ni * 8 + lc * 2;
                float v0 = acc[mi][ni][half * 2 + 0];
                float v1 = acc[mi][ni][half * 2 + 1];
                if (bias) { v0 += bias[c]; v1 += bias[c + 1]; }
                if (act == 1) {
                    v0 = fmaxf(v0, 0.f); v1 = fmaxf(v1, 0.f);
                } else if (act == 2) {
                    v0 = v0 > 0.f ? v0 : alpha[c] * v0;
                    v1 = v1 > 0.f ? v1 : alpha[c + 1] * v1;
                }
                *reinterpret_cast<float2*>(Cb + (size_t)r * N + c) = make_float2(v0, v1);
            }
        }
    }
}

// pred[M,2] = H[M,K] @ W[K,2] + b[2]   (warp per row)
__global__ void final_head_kernel(const float* __restrict__ H,
                                  const float* __restrict__ W,
                                  const float* __restrict__ b,
                                  float* __restrict__ out,
                                  int M, int K)
{
    __shared__ float w0[256], w1[256];
    const int tid = threadIdx.x;
    for (int i = tid; i < K; i += blockDim.x) {
        w0[i] = W[i * 2 + 0];
        w1[i] = W[i * 2 + 1];
    }
    __syncthreads();

    const int warp = tid >> 5;
    const int lane = tid & 31;
    const int row  = blockIdx.x * (blockDim.x >> 5) + warp;
    if (row >= M) return;

    const float* h = H + (size_t)row * K;
    float s0 = 0.f, s1 = 0.f;
    for (int c = lane; c < K; c += 32) {
        float v = h[c];
        s0 += v * w0[c];
        s1 += v * w1[c];
    }
#pragma unroll
    for (int o = 16; o; o >>= 1) {
        s0 += __shfl_xor_sync(0xFFFFFFFFu, s0, o);
        s1 += __shfl_xor_sync(0xFFFFFFFFu, s1, o);
    }
    if (lane == 0) {
        out[row * 2 + 0] = s0 + b[0];
        out[row * 2 + 1] = s1 + b[1];
    }
}

extern "C" void kernel_launch(void* const* d_in, const int* in_sizes, int n_in,
                              void* d_out, int out_size)
{
    const float* x   = (const float*)d_in[0];
    const float* adj = (const float*)d_in[1];
    const float* W1  = (const float*)d_in[2];
    const float* b1  = (const float*)d_in[3];
    const float* W2  = (const float*)d_in[4];
    const float* b2  = (const float*)d_in[5];
    const float* W3  = (const float*)d_in[6];
    const float* b3  = (const float*)d_in[7];
    const float* W4  = (const float*)d_in[8];
    const float* b4  = (const float*)d_in[9];
    const float* cW1 = (const float*)d_in[10];
    const float* cb1 = (const float*)d_in[11];
    const float* alp = (const float*)d_in[12];
    const float* cW2 = (const float*)d_in[13];
    const float* cb2 = (const float*)d_in[14];
    float* out = (float*)d_out;

    float *gh = nullptr, *gagg = nullptr, *gh2 = nullptr;
    cudaGetSymbolAddress((void**)&gh,   g_h);
    cudaGetSymbolAddress((void**)&gagg, g_agg);
    cudaGetSymbolAddress((void**)&gh2,  g_h2);

    const size_t smemBytes = SMEM_FLOATS * sizeof(float);
    static bool attrSet = false;
    if (!attrSet) {
        cudaFuncSetAttribute(tgemm_kernel, cudaFuncAttributeMaxDynamicSharedMemorySize,
                             (int)smemBytes);
        attrSet = true;
    }

    const int Bb = 32, Nn = 1024, D = 256, Hd = 512, Hh = 256;
    const int MB = Bb * Nn;  // 32768

    auto gemm = [&](const float* A1, int K1, const float* A2, int K2,
                    const float* W, const float* bias, float* C,
                    int M, int N, int batch, long sA, long sW, long sC,
                    int act, const float* alpha) {
        dim3 g(N / BN, M / BM, batch);
        tgemm_kernel<<<g, 256, smemBytes>>>(A1, K1, A2, K2, W, bias, C, M, N,
                                            sA, sW, sC, act, alpha);
    };

    // ---- Layer 1: agg = adj @ x ; h1 = relu([x|agg] W1 + b1) ----
    gemm(adj, Nn, nullptr, 0, x, nullptr, gagg, Nn, D, Bb,
         (long)Nn * Nn, (long)Nn * D, (long)Nn * D, 0, nullptr);
    gemm(x, D, gagg, D, W1, b1, gh, MB, Hd, 1, 0, 0, 0, 1, nullptr);

    // ---- Layer 2 ----
    gemm(adj, Nn, nullptr, 0, gh, nullptr, gagg, Nn, Hd, Bb,
         (long)Nn * Nn, (long)Nn * Hd, (long)Nn * Hd, 0, nullptr);
    gemm(gh, Hd, gagg, Hd, W2, b2, gh2, MB, Hd, 1, 0, 0, 0, 1, nullptr);

    // ---- Layer 3 ----
    gemm(adj, Nn, nullptr, 0, gh2, nullptr, gagg, Nn, Hd, Bb,
         (long)Nn * Nn, (long)Nn * Hd, (long)Nn * Hd, 0, nullptr);
    gemm(gh2, Hd, gagg, Hd, W3, b3, gh, MB, Hh, 1, 0, 0, 0, 1, nullptr);

    // ---- Layer 4 ----
    gemm(adj, Nn, nullptr, 0, gh, nullptr, gagg, Nn, Hh, Bb,
         (long)Nn * Nn, (long)Nn * Hh, (long)Nn * Hh, 0, nullptr);
    gemm(gh, Hh, gagg, Hh, W4, b4, gh2, MB, Hh, 1, 0, 0, 0, 1, nullptr);

    // ---- Classifier ----
    gemm(gh2, Hh, nullptr, 0, cW1, cb1, gh, MB, Hh, 1, 0, 0, 0, 2, alp);
    final_head_kernel<<<MB / 8, 256>>>(gh, cW2, cb2, out, MB, Hh);
}

// round 9
// speedup vs baseline: 1.9221x; 1.3505x over previous
#include <cuda_runtime.h>
#include <cuda_bf16.h>
#include <cstdint>
#include <cstddef>

// ---------------- scratch (no allocs allowed) ----------------
__device__ float g_h  [32u * 1024u * 512u];
__device__ float g_agg[32u * 1024u * 512u];
__device__ float g_h2 [32u * 1024u * 512u];

// ---------------- smem layout (bytes) ----------------
// A tiles: [128 m][32 k] bf16, row stride 80B (64B data + 16B pad, 5r%8 distinct)
// B tiles: [32 k][128 n] bf16, row stride 272B (256B data + 16B pad, 17r%8 distinct)
#define A_STRIDE_B 80
#define B_STRIDE_B 272
#define ABUF 10240          // 128*80
#define BBUF 8704           // 32*272
#define A_HI_OFF  0         // [2 buf]
#define A_MID_OFF 20480
#define B_HI_OFF  40960
#define B_MID_OFF 58368
#define SMEM_BYTES 75776

__device__ __forceinline__ uint32_t smem_u32(const void* p) {
    uint32_t a;
    asm("{ .reg .u64 t; cvta.to.shared.u64 t, %1; cvt.u32.u64 %0, t; }" : "=r"(a) : "l"(p));
    return a;
}

__device__ __forceinline__ void ldsm_x4(uint32_t r[4], uint32_t addr) {
    asm volatile("ldmatrix.sync.aligned.m8n8.x4.shared.b16 {%0,%1,%2,%3}, [%4];"
                 : "=r"(r[0]), "=r"(r[1]), "=r"(r[2]), "=r"(r[3]) : "r"(addr));
}
__device__ __forceinline__ void ldsm_x4_trans(uint32_t r[4], uint32_t addr) {
    asm volatile("ldmatrix.sync.aligned.m8n8.x4.trans.shared.b16 {%0,%1,%2,%3}, [%4];"
                 : "=r"(r[0]), "=r"(r[1]), "=r"(r[2]), "=r"(r[3]) : "r"(addr));
}
__device__ __forceinline__ void mma_bf16(float c[4], const uint32_t a[4],
                                         uint32_t b0, uint32_t b1) {
    asm volatile(
        "mma.sync.aligned.m16n8k16.row.col.f32.bf16.bf16.f32 "
        "{%0,%1,%2,%3}, {%4,%5,%6,%7}, {%8,%9}, {%0,%1,%2,%3};"
        : "+f"(c[0]), "+f"(c[1]), "+f"(c[2]), "+f"(c[3])
        : "r"(a[0]), "r"(a[1]), "r"(a[2]), "r"(a[3]), "r"(b0), "r"(b1));
}

// split float4 -> (hi bf16x2 pair, mid bf16x2 pair), memory order lo-first
__device__ __forceinline__ void split4(float4 v, uint2& hi, uint2& mid) {
    __nv_bfloat162 h01 = __floats2bfloat162_rn(v.x, v.y);
    __nv_bfloat162 h23 = __floats2bfloat162_rn(v.z, v.w);
    float2 f01 = __bfloat1622float2(h01);
    float2 f23 = __bfloat1622float2(h23);
    __nv_bfloat162 m01 = __floats2bfloat162_rn(v.x - f01.x, v.y - f01.y);
    __nv_bfloat162 m23 = __floats2bfloat162_rn(v.z - f23.x, v.w - f23.y);
    hi  = make_uint2(*reinterpret_cast<uint32_t*>(&h01), *reinterpret_cast<uint32_t*>(&h23));
    mid = make_uint2(*reinterpret_cast<uint32_t*>(&m01), *reinterpret_cast<uint32_t*>(&m23));
}

// ---------------------------------------------------------------------------
// C[M,N] = act( [A1|A2] @ W + bias ), bf16x4 emulated fp32 on mma.sync.m16n8k16.
// Tile 128x128, BK=32. A row-major (concat K1+K2); W (K x N) row-major.
// Batched via blockIdx.z. act: 0 none, 1 relu, 2 prelu(alpha per col).
// ---------------------------------------------------------------------------
__global__ __launch_bounds__(256)
void bgemm_kernel(const float* __restrict__ A1, int K1,
                  const float* __restrict__ A2, int K2,
                  const float* __restrict__ Wm,
                  const float* __restrict__ bias,
                  float* __restrict__ C,
                  int N,
                  long sA, long sB, long sC,
                  int act, const float* __restrict__ alpha)
{
    extern __shared__ __align__(1024) char smem[];
    const uint32_t sb = smem_u32(smem);
    const int K  = K1 + K2;
    const int nc = K >> 5;
    const int bz = blockIdx.z;
    const float* A1b = A1 + (size_t)bz * sA;
    const float* Bb  = Wm + (size_t)bz * sB;
    float*       Cb  = C  + (size_t)bz * sC;

    const int tid  = threadIdx.x;
    const int wid  = tid >> 5;
    const int lane = tid & 31;
    const int warpM = wid >> 1;          // 0..3 -> 32 rows
    const int warpN = wid & 1;           // 0..1 -> 64 cols
    const int lr = lane >> 2, lc = lane & 3;

    const int rowBase = blockIdx.y * 128;
    const int colBase = blockIdx.x * 128;

    // ldmatrix lane offsets
    const uint32_t aLane = (uint32_t)((lane & 15) * A_STRIDE_B + (lane >> 4) * 16);
    const uint32_t bLane = (uint32_t)((((lane & 7) + ((lane >> 3) & 1) * 8)) * B_STRIDE_B
                                      + ((lane >> 4) & 1) * 16);

    float acc[2][8][4];
#pragma unroll
    for (int mi = 0; mi < 2; mi++)
#pragma unroll
        for (int ni = 0; ni < 8; ni++)
#pragma unroll
            for (int j = 0; j < 4; j++) acc[mi][ni][j] = 0.f;

    // fetch mapping: A: row r = tid>>1 (0..127), kq = (tid&1)*16, 4 float4
    //                B: k = tid>>3 (0..31),  n16 = (tid&7)*16,   4 float4
    const int aR  = tid >> 1, aKq = (tid & 1) * 16;
    const int bK  = tid >> 3, bN16 = (tid & 7) * 16;

    float4 av[4], bv[4];

    auto fetch = [&](int ch) {
        const int kc = ch << 5;
        const float* Ap; int lda, ko;
        if (kc < K1) { Ap = A1b; lda = K1; ko = kc; }
        else         { Ap = A2;  lda = K2; ko = kc - K1; }
        const float* arow = Ap + (size_t)(rowBase + aR) * lda + ko + aKq;
#pragma unroll
        for (int i = 0; i < 4; i++)
            av[i] = *reinterpret_cast<const float4*>(arow + 4 * i);
        const float* brow = Bb + (size_t)(kc + bK) * N + colBase + bN16;
#pragma unroll
        for (int i = 0; i < 4; i++)
            bv[i] = *reinterpret_cast<const float4*>(brow + 4 * i);
    };

    auto stage = [&](int buf) {
        char* sAh = smem + A_HI_OFF  + buf * ABUF;
        char* sAm = smem + A_MID_OFF + buf * ABUF;
        char* sBh = smem + B_HI_OFF  + buf * BBUF;
        char* sBm = smem + B_MID_OFF + buf * BBUF;
        const int aOff = aR * A_STRIDE_B + aKq * 2;
        const int bOff = bK * B_STRIDE_B + bN16 * 2;
#pragma unroll
        for (int i = 0; i < 4; i++) {
            uint2 hi, mid;
            split4(av[i], hi, mid);
            *reinterpret_cast<uint2*>(sAh + aOff + 8 * i) = hi;
            *reinterpret_cast<uint2*>(sAm + aOff + 8 * i) = mid;
        }
#pragma unroll
        for (int i = 0; i < 4; i++) {
            uint2 hi, mid;
            split4(bv[i], hi, mid);
            *reinterpret_cast<uint2*>(sBh + bOff + 8 * i) = hi;
            *reinterpret_cast<uint2*>(sBm + bOff + 8 * i) = mid;
        }
    };

    fetch(0);
    stage(0);
    __syncthreads();

    for (int ch = 0; ch < nc; ++ch) {
        const int buf = ch & 1;
        if (ch + 1 < nc) fetch(ch + 1);

        const uint32_t aHiB = sb + A_HI_OFF  + buf * ABUF + (uint32_t)(warpM * 32) * A_STRIDE_B + aLane;
        const uint32_t aMiB = sb + A_MID_OFF + buf * ABUF + (uint32_t)(warpM * 32) * A_STRIDE_B + aLane;
        const uint32_t bHiB = sb + B_HI_OFF  + buf * BBUF + (uint32_t)(warpN * 128) + bLane;
        const uint32_t bMiB = sb + B_MID_OFF + buf * BBUF + (uint32_t)(warpN * 128) + bLane;

#pragma unroll
        for (int ks = 0; ks < 2; ks++) {
            uint32_t ah[2][4], am[2][4];
#pragma unroll
            for (int mi = 0; mi < 2; mi++) {
                ldsm_x4(ah[mi], aHiB + mi * 16 * A_STRIDE_B + ks * 32);
                ldsm_x4(am[mi], aMiB + mi * 16 * A_STRIDE_B + ks * 32);
            }
#pragma unroll
            for (int g = 0; g < 4; g++) {
                uint32_t bh[4], bm[4];
                ldsm_x4_trans(bh, bHiB + ks * 16 * B_STRIDE_B + g * 32);
                ldsm_x4_trans(bm, bMiB + ks * 16 * B_STRIDE_B + g * 32);
#pragma unroll
                for (int sub = 0; sub < 2; sub++) {
                    const uint32_t b0h = bh[sub * 2], b1h = bh[sub * 2 + 1];
                    const uint32_t b0m = bm[sub * 2], b1m = bm[sub * 2 + 1];
                    const int ni = g * 2 + sub;
#pragma unroll
                    for (int mi = 0; mi < 2; mi++) {
                        mma_bf16(acc[mi][ni], ah[mi], b0h, b1h);
                        mma_bf16(acc[mi][ni], am[mi], b0h, b1h);
                        mma_bf16(acc[mi][ni], ah[mi], b0m, b1m);
                        mma_bf16(acc[mi][ni], am[mi], b0m, b1m);
                    }
                }
            }
        }

        __syncthreads();
        if (ch + 1 < nc) {
            stage(buf ^ 1);
            __syncthreads();
        }
    }

    // Epilogue: bias + activation, float2 stores (m16n8 C fragment layout)
#pragma unroll
    for (int mi = 0; mi < 2; mi++) {
#pragma unroll
        for (int ni = 0; ni < 8; ni++) {
#pragma unroll
            for (int half = 0; half < 2; half++) {
                int r = rowBase + warpM * 32 + mi * 16 + lr + half * 8;
                int c = colBase + warpN * 64 + ni * 8 + lc * 2;
                float v0 = acc[mi][ni][half * 2 + 0];
                float v1 = acc[mi][ni][half * 2 + 1];
                if (bias) { v0 += bias[c]; v1 += bias[c + 1]; }
                if (act == 1) {
                    v0 = fmaxf(v0, 0.f); v1 = fmaxf(v1, 0.f);
                } else if (act == 2) {
                    v0 = v0 > 0.f ? v0 : alpha[c] * v0;
                    v1 = v1 > 0.f ? v1 : alpha[c + 1] * v1;
                }
                *reinterpret_cast<float2*>(Cb + (size_t)r * N + c) = make_float2(v0, v1);
            }
        }
    }
}

// pred[M,2] = H[M,K] @ W[K,2] + b[2]   (warp per row)
__global__ void final_head_kernel(const float* __restrict__ H,
                                  const float* __restrict__ W,
                                  const float* __restrict__ b,
                                  float* __restrict__ out,
                                  int M, int K)
{
    __shared__ float w0[256], w1[256];
    const int tid = threadIdx.x;
    for (int i = tid; i < K; i += blockDim.x) {
        w0[i] = W[i * 2 + 0];
        w1[i] = W[i * 2 + 1];
    }
    __syncthreads();

    const int warp = tid >> 5;
    const int lane = tid & 31;
    const int row  = blockIdx.x * (blockDim.x >> 5) + warp;
    if (row >= M) return;

    const float* h = H + (size_t)row * K;
    float s0 = 0.f, s1 = 0.f;
    for (int c = lane; c < K; c += 32) {
        float v = h[c];
        s0 += v * w0[c];
        s1 += v * w1[c];
    }
#pragma unroll
    for (int o = 16; o; o >>= 1) {
        s0 += __shfl_xor_sync(0xFFFFFFFFu, s0, o);
        s1 += __shfl_xor_sync(0xFFFFFFFFu, s1, o);
    }
    if (lane == 0) {
        out[row * 2 + 0] = s0 + b[0];
        out[row * 2 + 1] = s1 + b[1];
    }
}

extern "C" void kernel_launch(void* const* d_in, const int* in_sizes, int n_in,
                              void* d_out, int out_size)
{
    const float* x   = (const float*)d_in[0];
    const float* adj = (const float*)d_in[1];
    const float* W1  = (const float*)d_in[2];
    const float* b1  = (const float*)d_in[3];
    const float* W2  = (const float*)d_in[4];
    const float* b2  = (const float*)d_in[5];
    const float* W3  = (const float*)d_in[6];
    const float* b3  = (const float*)d_in[7];
    const float* W4  = (const float*)d_in[8];
    const float* b4  = (const float*)d_in[9];
    const float* cW1 = (const float*)d_in[10];
    const float* cb1 = (const float*)d_in[11];
    const float* alp = (const float*)d_in[12];
    const float* cW2 = (const float*)d_in[13];
    const float* cb2 = (const float*)d_in[14];
    float* out = (float*)d_out;

    float *gh = nullptr, *gagg = nullptr, *gh2 = nullptr;
    cudaGetSymbolAddress((void**)&gh,   g_h);
    cudaGetSymbolAddress((void**)&gagg, g_agg);
    cudaGetSymbolAddress((void**)&gh2,  g_h2);

    static bool attrSet = false;
    if (!attrSet) {
        cudaFuncSetAttribute(bgemm_kernel, cudaFuncAttributeMaxDynamicSharedMemorySize,
                             SMEM_BYTES);
        attrSet = true;
    }

    const int Bb = 32, Nn = 1024, D = 256, Hd = 512, Hh = 256;
    const int MB = Bb * Nn;  // 32768

    auto gemm = [&](const float* A1, int K1, const float* A2, int K2,
                    const float* W, const float* bias, float* C,
                    int M, int N, int batch, long sA, long sB, long sC,
                    int act, const float* alpha) {
        dim3 g(N / 128, M / 128, batch);
        bgemm_kernel<<<g, 256, SMEM_BYTES>>>(A1, K1, A2, K2, W, bias, C, N,
                                             sA, sB, sC, act, alpha);
    };

    // ---- Layer 1: agg = adj @ x ; h1 = relu([x|agg] W1 + b1) ----
    gemm(adj, Nn, nullptr, 0, x, nullptr, gagg, Nn, D, Bb,
         (long)Nn * Nn, (long)Nn * D, (long)Nn * D, 0, nullptr);
    gemm(x, D, gagg, D, W1, b1, gh, MB, Hd, 1, 0, 0, 0, 1, nullptr);

    // ---- Layer 2 ----
    gemm(adj, Nn, nullptr, 0, gh, nullptr, gagg, Nn, Hd, Bb,
         (long)Nn * Nn, (long)Nn * Hd, (long)Nn * Hd, 0, nullptr);
    gemm(gh, Hd, gagg, Hd, W2, b2, gh2, MB, Hd, 1, 0, 0, 0, 1, nullptr);

    // ---- Layer 3 ----
    gemm(adj, Nn, nullptr, 0, gh2, nullptr, gagg, Nn, Hd, Bb,
         (long)Nn * Nn, (long)Nn * Hd, (long)Nn * Hd, 0, nullptr);
    gemm(gh2, Hd, gagg, Hd, W3, b3, gh, MB, Hh, 1, 0, 0, 0, 1, nullptr);

    // ---- Layer 4 ----
    gemm(adj, Nn, nullptr, 0, gh, nullptr, gagg, Nn, Hh, Bb,
         (long)Nn * Nn, (long)Nn * Hh, (long)Nn * Hh, 0, nullptr);
    gemm(gh, Hh, gagg, Hh, W4, b4, gh2, MB, Hh, 1, 0, 0, 0, 1, nullptr);

    // ---- Classifier ----
    gemm(gh2, Hh, nullptr, 0, cW1, cb1, gh, MB, Hh, 1, 0, 0, 0, 2, alp);
    final_head_kernel<<<MB / 8, 256>>>(gh, cW2, cb2, out, MB, Hh);
}

// round 11
// speedup vs baseline: 2.3235x; 1.2088x over previous
#include <cuda_runtime.h>
#include <cuda_bf16.h>
#include <cstdint>
#include <cstddef>

// ---------------- scratch (no allocs allowed) ----------------
__device__ float g_h  [32u * 1024u * 512u];
__device__ float g_agg[32u * 1024u * 512u];
__device__ float g_h2 [32u * 1024u * 512u];

// ---------------- smem layout (bytes) ----------------
// A tiles: [128 m][32 k] bf16, row stride 80B (64B data + 16B pad, 5r%8 distinct)
// B tiles: [32 k][128 n] bf16, row stride 272B (256B data + 16B pad, 17r%8 distinct)
#define A_STRIDE_B 80
#define B_STRIDE_B 272
#define ABUF 10240          // 128*80
#define BBUF 8704           // 32*272
#define A_HI_OFF  0         // [2 buf]
#define A_MID_OFF 20480
#define B_HI_OFF  40960
#define B_MID_OFF 58368
#define SMEM_BYTES 75776

__device__ __forceinline__ uint32_t smem_u32(const void* p) {
    uint32_t a;
    asm("{ .reg .u64 t; cvta.to.shared.u64 t, %1; cvt.u32.u64 %0, t; }" : "=r"(a) : "l"(p));
    return a;
}

__device__ __forceinline__ void ldsm_x4(uint32_t r[4], uint32_t addr) {
    asm volatile("ldmatrix.sync.aligned.m8n8.x4.shared.b16 {%0,%1,%2,%3}, [%4];"
                 : "=r"(r[0]), "=r"(r[1]), "=r"(r[2]), "=r"(r[3]) : "r"(addr));
}
__device__ __forceinline__ void ldsm_x4_trans(uint32_t r[4], uint32_t addr) {
    asm volatile("ldmatrix.sync.aligned.m8n8.x4.trans.shared.b16 {%0,%1,%2,%3}, [%4];"
                 : "=r"(r[0]), "=r"(r[1]), "=r"(r[2]), "=r"(r[3]) : "r"(addr));
}
__device__ __forceinline__ void mma_bf16(float c[4], const uint32_t a[4],
                                         uint32_t b0, uint32_t b1) {
    asm volatile(
        "mma.sync.aligned.m16n8k16.row.col.f32.bf16.bf16.f32 "
        "{%0,%1,%2,%3}, {%4,%5,%6,%7}, {%8,%9}, {%0,%1,%2,%3};"
        : "+f"(c[0]), "+f"(c[1]), "+f"(c[2]), "+f"(c[3])
        : "r"(a[0]), "r"(a[1]), "r"(a[2]), "r"(a[3]), "r"(b0), "r"(b1));
}

// split float4 -> (hi bf16x2 pair, mid bf16x2 pair), memory order lo-first
__device__ __forceinline__ void split4(float4 v, uint2& hi, uint2& mid) {
    __nv_bfloat162 h01 = __floats2bfloat162_rn(v.x, v.y);
    __nv_bfloat162 h23 = __floats2bfloat162_rn(v.z, v.w);
    float2 f01 = __bfloat1622float2(h01);
    float2 f23 = __bfloat1622float2(h23);
    __nv_bfloat162 m01 = __floats2bfloat162_rn(v.x - f01.x, v.y - f01.y);
    __nv_bfloat162 m23 = __floats2bfloat162_rn(v.z - f23.x, v.w - f23.y);
    hi  = make_uint2(*reinterpret_cast<uint32_t*>(&h01), *reinterpret_cast<uint32_t*>(&h23));
    mid = make_uint2(*reinterpret_cast<uint32_t*>(&m01), *reinterpret_cast<uint32_t*>(&m23));
}

// ---------------------------------------------------------------------------
// C[M,N] = act( [A1|A2] @ W + bias ), bf16x3 emulated fp32 on mma.sync.m16n8k16.
// (hi*hi + mid*hi + hi*mid; mid*mid dropped, ~2^-16 rel contribution)
// Tile 128x128, BK=32. A row-major (concat K1+K2); W (K x N) row-major.
// Batched via blockIdx.z. act: 0 none, 1 relu, 2 prelu(alpha per col).
// ---------------------------------------------------------------------------
__global__ __launch_bounds__(256, 2)
void bgemm_kernel(const float* __restrict__ A1, int K1,
                  const float* __restrict__ A2, int K2,
                  const float* __restrict__ Wm,
                  const float* __restrict__ bias,
                  float* __restrict__ C,
                  int N,
                  long sA, long sB, long sC,
                  int act, const float* __restrict__ alpha)
{
    extern __shared__ __align__(1024) char smem[];
    const uint32_t sb = smem_u32(smem);
    const int K  = K1 + K2;
    const int nc = K >> 5;
    const int bz = blockIdx.z;
    const float* A1b = A1 + (size_t)bz * sA;
    const float* Bb  = Wm + (size_t)bz * sB;
    float*       Cb  = C  + (size_t)bz * sC;

    const int tid  = threadIdx.x;
    const int wid  = tid >> 5;
    const int lane = tid & 31;
    const int warpM = wid >> 1;          // 0..3 -> 32 rows
    const int warpN = wid & 1;           // 0..1 -> 64 cols
    const int lr = lane >> 2, lc = lane & 3;

    const int rowBase = blockIdx.y * 128;
    const int colBase = blockIdx.x * 128;

    // ldmatrix lane offsets
    const uint32_t aLane = (uint32_t)((lane & 15) * A_STRIDE_B + (lane >> 4) * 16);
    const uint32_t bLane = (uint32_t)((((lane & 7) + ((lane >> 3) & 1) * 8)) * B_STRIDE_B
                                      + ((lane >> 4) & 1) * 16);

    float acc[2][8][4];
#pragma unroll
    for (int mi = 0; mi < 2; mi++)
#pragma unroll
        for (int ni = 0; ni < 8; ni++)
#pragma unroll
            for (int j = 0; j < 4; j++) acc[mi][ni][j] = 0.f;

    // fetch mapping: A: row r = tid>>1 (0..127), kq = (tid&1)*16, 4 float4
    //                B: k = tid>>3 (0..31),  n16 = (tid&7)*16,   4 float4
    const int aR  = tid >> 1, aKq = (tid & 1) * 16;
    const int bK  = tid >> 3, bN16 = (tid & 7) * 16;

    float4 av[4], bv[4];

    auto fetch = [&](int ch) {
        const int kc = ch << 5;
        const float* Ap; int lda, ko;
        if (kc < K1) { Ap = A1b; lda = K1; ko = kc; }
        else         { Ap = A2;  lda = K2; ko = kc - K1; }
        const float* arow = Ap + (size_t)(rowBase + aR) * lda + ko + aKq;
#pragma unroll
        for (int i = 0; i < 4; i++)
            av[i] = *reinterpret_cast<const float4*>(arow + 4 * i);
        const float* brow = Bb + (size_t)(kc + bK) * N + colBase + bN16;
#pragma unroll
        for (int i = 0; i < 4; i++)
            bv[i] = *reinterpret_cast<const float4*>(brow + 4 * i);
    };

    auto stage = [&](int buf) {
        char* sAh = smem + A_HI_OFF  + buf * ABUF;
        char* sAm = smem + A_MID_OFF + buf * ABUF;
        char* sBh = smem + B_HI_OFF  + buf * BBUF;
        char* sBm = smem + B_MID_OFF + buf * BBUF;
        const int aOff = aR * A_STRIDE_B + aKq * 2;
        const int bOff = bK * B_STRIDE_B + bN16 * 2;
#pragma unroll
        for (int i = 0; i < 4; i++) {
            uint2 hi, mid;
            split4(av[i], hi, mid);
            *reinterpret_cast<uint2*>(sAh + aOff + 8 * i) = hi;
            *reinterpret_cast<uint2*>(sAm + aOff + 8 * i) = mid;
        }
#pragma unroll
        for (int i = 0; i < 4; i++) {
            uint2 hi, mid;
            split4(bv[i], hi, mid);
            *reinterpret_cast<uint2*>(sBh + bOff + 8 * i) = hi;
            *reinterpret_cast<uint2*>(sBm + bOff + 8 * i) = mid;
        }
    };

    fetch(0);
    stage(0);
    __syncthreads();

    for (int ch = 0; ch < nc; ++ch) {
        const int buf = ch & 1;
        if (ch + 1 < nc) fetch(ch + 1);

        const uint32_t aHiB = sb + A_HI_OFF  + buf * ABUF + (uint32_t)(warpM * 32) * A_STRIDE_B + aLane;
        const uint32_t aMiB = sb + A_MID_OFF + buf * ABUF + (uint32_t)(warpM * 32) * A_STRIDE_B + aLane;
        const uint32_t bHiB = sb + B_HI_OFF  + buf * BBUF + (uint32_t)(warpN * 128) + bLane;
        const uint32_t bMiB = sb + B_MID_OFF + buf * BBUF + (uint32_t)(warpN * 128) + bLane;

#pragma unroll
        for (int ks = 0; ks < 2; ks++) {
            uint32_t ah[2][4], am[2][4];
#pragma unroll
            for (int mi = 0; mi < 2; mi++) {
                ldsm_x4(ah[mi], aHiB + mi * 16 * A_STRIDE_B + ks * 32);
                ldsm_x4(am[mi], aMiB + mi * 16 * A_STRIDE_B + ks * 32);
            }
#pragma unroll
            for (int g = 0; g < 4; g++) {
                uint32_t bh[4], bm[4];
                ldsm_x4_trans(bh, bHiB + ks * 16 * B_STRIDE_B + g * 32);
                ldsm_x4_trans(bm, bMiB + ks * 16 * B_STRIDE_B + g * 32);
#pragma unroll
                for (int sub = 0; sub < 2; sub++) {
                    const uint32_t b0h = bh[sub * 2], b1h = bh[sub * 2 + 1];
                    const uint32_t b0m = bm[sub * 2], b1m = bm[sub * 2 + 1];
                    const int ni = g * 2 + sub;
#pragma unroll
                    for (int mi = 0; mi < 2; mi++) {
                        mma_bf16(acc[mi][ni], ah[mi], b0h, b1h);
                        mma_bf16(acc[mi][ni], am[mi], b0h, b1h);
                        mma_bf16(acc[mi][ni], ah[mi], b0m, b1m);
                    }
                }
            }
        }

        __syncthreads();
        if (ch + 1 < nc) {
            stage(buf ^ 1);
            __syncthreads();
        }
    }

    // Epilogue: bias + activation, float2 stores (m16n8 C fragment layout)
#pragma unroll
    for (int mi = 0; mi < 2; mi++) {
#pragma unroll
        for (int ni = 0; ni < 8; ni++) {
#pragma unroll
            for (int half = 0; half < 2; half++) {
                int r = rowBase + warpM * 32 + mi * 16 + lr + half * 8;
                int c = colBase + warpN * 64 + ni * 8 + lc * 2;
                float v0 = acc[mi][ni][half * 2 + 0];
                float v1 = acc[mi][ni][half * 2 + 1];
                if (bias) { v0 += bias[c]; v1 += bias[c + 1]; }
                if (act == 1) {
                    v0 = fmaxf(v0, 0.f); v1 = fmaxf(v1, 0.f);
                } else if (act == 2) {
                    v0 = v0 > 0.f ? v0 : alpha[c] * v0;
                    v1 = v1 > 0.f ? v1 : alpha[c + 1] * v1;
                }
                *reinterpret_cast<float2*>(Cb + (size_t)r * N + c) = make_float2(v0, v1);
            }
        }
    }
}

// pred[M,2] = H[M,K] @ W[K,2] + b[2]   (warp per row)
__global__ void final_head_kernel(const float* __restrict__ H,
                                  const float* __restrict__ W,
                                  const float* __restrict__ b,
                                  float* __restrict__ out,
                                  int M, int K)
{
    __shared__ float w0[256], w1[256];
    const int tid = threadIdx.x;
    for (int i = tid; i < K; i += blockDim.x) {
        w0[i] = W[i * 2 + 0];
        w1[i] = W[i * 2 + 1];
    }
    __syncthreads();

    const int warp = tid >> 5;
    const int lane = tid & 31;
    const int row  = blockIdx.x * (blockDim.x >> 5) + warp;
    if (row >= M) return;

    const float* h = H + (size_t)row * K;
    float s0 = 0.f, s1 = 0.f;
    for (int c = lane; c < K; c += 32) {
        float v = h[c];
        s0 += v * w0[c];
        s1 += v * w1[c];
    }
#pragma unroll
    for (int o = 16; o; o >>= 1) {
        s0 += __shfl_xor_sync(0xFFFFFFFFu, s0, o);
        s1 += __shfl_xor_sync(0xFFFFFFFFu, s1, o);
    }
    if (lane == 0) {
        out[row * 2 + 0] = s0 + b[0];
        out[row * 2 + 1] = s1 + b[1];
    }
}

extern "C" void kernel_launch(void* const* d_in, const int* in_sizes, int n_in,
                              void* d_out, int out_size)
{
    const float* x   = (const float*)d_in[0];
    const float* adj = (const float*)d_in[1];
    const float* W1  = (const float*)d_in[2];
    const float* b1  = (const float*)d_in[3];
    const float* W2  = (const float*)d_in[4];
    const float* b2  = (const float*)d_in[5];
    const float* W3  = (const float*)d_in[6];
    const float* b3  = (const float*)d_in[7];
    const float* W4  = (const float*)d_in[8];
    const float* b4  = (const float*)d_in[9];
    const float* cW1 = (const float*)d_in[10];
    const float* cb1 = (const float*)d_in[11];
    const float* alp = (const float*)d_in[12];
    const float* cW2 = (const float*)d_in[13];
    const float* cb2 = (const float*)d_in[14];
    float* out = (float*)d_out;

    float *gh = nullptr, *gagg = nullptr, *gh2 = nullptr;
    cudaGetSymbolAddress((void**)&gh,   g_h);
    cudaGetSymbolAddress((void**)&gagg, g_agg);
    cudaGetSymbolAddress((void**)&gh2,  g_h2);

    static bool attrSet = false;
    if (!attrSet) {
        cudaFuncSetAttribute(bgemm_kernel, cudaFuncAttributeMaxDynamicSharedMemorySize,
                             SMEM_BYTES);
        attrSet = true;
    }

    const int Bb = 32, Nn = 1024, D = 256, Hd = 512, Hh = 256;
    const int MB = Bb * Nn;  // 32768

    auto gemm = [&](const float* A1, int K1, const float* A2, int K2,
                    const float* W, const float* bias, float* C,
                    int M, int N, int batch, long sA, long sB, long sC,
                    int act, const float* alpha) {
        dim3 g(N / 128, M / 128, batch);
        bgemm_kernel<<<g, 256, SMEM_BYTES>>>(A1, K1, A2, K2, W, bias, C, N,
                                             sA, sB, sC, act, alpha);
    };

    // ---- Layer 1: agg = adj @ x ; h1 = relu([x|agg] W1 + b1) ----
    gemm(adj, Nn, nullptr, 0, x, nullptr, gagg, Nn, D, Bb,
         (long)Nn * Nn, (long)Nn * D, (long)Nn * D, 0, nullptr);
    gemm(x, D, gagg, D, W1, b1, gh, MB, Hd, 1, 0, 0, 0, 1, nullptr);

    // ---- Layer 2 ----
    gemm(adj, Nn, nullptr, 0, gh, nullptr, gagg, Nn, Hd, Bb,
         (long)Nn * Nn, (long)Nn * Hd, (long)Nn * Hd, 0, nullptr);
    gemm(gh, Hd, gagg, Hd, W2, b2, gh2, MB, Hd, 1, 0, 0, 0, 1, nullptr);

    // ---- Layer 3 ----
    gemm(adj, Nn, nullptr, 0, gh2, nullptr, gagg, Nn, Hd, Bb,
         (long)Nn * Nn, (long)Nn * Hd, (long)Nn * Hd, 0, nullptr);
    gemm(gh2, Hd, gagg, Hd, W3, b3, gh, MB, Hh, 1, 0, 0, 0, 1, nullptr);

    // ---- Layer 4 ----
    gemm(adj, Nn, nullptr, 0, gh, nullptr, gagg, Nn, Hh, Bb,
         (long)Nn * Nn, (long)Nn * Hh, (long)Nn * Hh, 0, nullptr);
    gemm(gh, Hh, gagg, Hh, W4, b4, gh2, MB, Hh, 1, 0, 0, 0, 1, nullptr);

    // ---- Classifier ----
    gemm(gh2, Hh, nullptr, 0, cW1, cb1, gh, MB, Hh, 1, 0, 0, 0, 2, alp);
    final_head_kernel<<<MB / 8, 256>>>(gh, cW2, cb2, out, MB, Hh);
}

// round 12
// speedup vs baseline: 2.7985x; 1.2044x over previous
#include <cuda_runtime.h>
#include <cuda_bf16.h>
#include <cstdint>
#include <cstddef>

// ---------------- bf16 scratch (no allocs allowed) ----------------
__device__ __nv_bfloat16 s_adj_h[32u*1024u*1024u];
__device__ __nv_bfloat16 s_adj_m[32u*1024u*1024u];
__device__ __nv_bfloat16 s_x_h[32u*1024u*256u];
__device__ __nv_bfloat16 s_x_m[32u*1024u*256u];
__device__ __nv_bfloat16 s_hA_h[32u*1024u*512u];
__device__ __nv_bfloat16 s_hA_m[32u*1024u*512u];
__device__ __nv_bfloat16 s_hB_h[32u*1024u*512u];
__device__ __nv_bfloat16 s_hB_m[32u*1024u*512u];
__device__ __nv_bfloat16 s_ag_h[32u*1024u*512u];
__device__ __nv_bfloat16 s_ag_m[32u*1024u*512u];
__device__ __nv_bfloat16 s_w_h[2u<<20];
__device__ __nv_bfloat16 s_w_m[2u<<20];

// ---------------- smem geometry (bytes) ----------------
// A: [128 m][32 k] bf16, row stride 80B. B: [32 k][128 n] bf16, row stride 272B.
#define A_STRIDE_B 80
#define B_STRIDE_B 272
#define A_HI_S  0
#define A_MID_S 10240
#define B_HI_S  20480
#define B_MID_S 29184
#define STG_BYTES 37888
#define NST 3
#define SMEM_BYTES (NST * STG_BYTES)   // 113664

__device__ __forceinline__ uint32_t smem_u32(const void* p) {
    uint32_t a;
    asm("{ .reg .u64 t; cvta.to.shared.u64 t, %1; cvt.u32.u64 %0, t; }" : "=r"(a) : "l"(p));
    return a;
}
__device__ __forceinline__ void cpa16(uint32_t dst, const void* src) {
    asm volatile("cp.async.cg.shared.global [%0], [%1], 16;" :: "r"(dst), "l"(src));
}
#define CPA_COMMIT() asm volatile("cp.async.commit_group;" ::: "memory")
#define CPA_WAIT1()  asm volatile("cp.async.wait_group 1;" ::: "memory")

__device__ __forceinline__ void ldsm_x4(uint32_t r[4], uint32_t addr) {
    asm volatile("ldmatrix.sync.aligned.m8n8.x4.shared.b16 {%0,%1,%2,%3}, [%4];"
                 : "=r"(r[0]), "=r"(r[1]), "=r"(r[2]), "=r"(r[3]) : "r"(addr));
}
__device__ __forceinline__ void ldsm_x4_trans(uint32_t r[4], uint32_t addr) {
    asm volatile("ldmatrix.sync.aligned.m8n8.x4.trans.shared.b16 {%0,%1,%2,%3}, [%4];"
                 : "=r"(r[0]), "=r"(r[1]), "=r"(r[2]), "=r"(r[3]) : "r"(addr));
}
__device__ __forceinline__ void mma_bf16(float c[4], const uint32_t a[4],
                                         uint32_t b0, uint32_t b1) {
    asm volatile(
        "mma.sync.aligned.m16n8k16.row.col.f32.bf16.bf16.f32 "
        "{%0,%1,%2,%3}, {%4,%5,%6,%7}, {%8,%9}, {%0,%1,%2,%3};"
        : "+f"(c[0]), "+f"(c[1]), "+f"(c[2]), "+f"(c[3])
        : "r"(a[0]), "r"(a[1]), "r"(a[2]), "r"(a[3]), "r"(b0), "r"(b1));
}

// ---------------------------------------------------------------------------
// Split fp32 -> bf16 hi + bf16 mid (residual). n divisible by 1024.
// ---------------------------------------------------------------------------
__global__ void split_kernel(const float* __restrict__ in,
                             __nv_bfloat16* __restrict__ hi,
                             __nv_bfloat16* __restrict__ mid, int n)
{
    int i = blockIdx.x * blockDim.x + threadIdx.x;
    float4 v = reinterpret_cast<const float4*>(in)[i];
    __nv_bfloat162 h01 = __floats2bfloat162_rn(v.x, v.y);
    __nv_bfloat162 h23 = __floats2bfloat162_rn(v.z, v.w);
    float2 f01 = __bfloat1622float2(h01);
    float2 f23 = __bfloat1622float2(h23);
    __nv_bfloat162 m01 = __floats2bfloat162_rn(v.x - f01.x, v.y - f01.y);
    __nv_bfloat162 m23 = __floats2bfloat162_rn(v.z - f23.x, v.w - f23.y);
    reinterpret_cast<__nv_bfloat162*>(hi)[2*i]   = h01;
    reinterpret_cast<__nv_bfloat162*>(hi)[2*i+1] = h23;
    reinterpret_cast<__nv_bfloat162*>(mid)[2*i]   = m01;
    reinterpret_cast<__nv_bfloat162*>(mid)[2*i+1] = m23;
}

// ---------------------------------------------------------------------------
// C = act([A1|A2] @ B + bias), bf16x3 on mma.sync, cp.async 3-stage pipeline.
// All matrix operands pre-split bf16 (hi/mid). Output written as bf16 hi/mid.
// A row-major [M][K*], B k-major [K][N]. Batched via blockIdx.z.
// ---------------------------------------------------------------------------
__global__ __launch_bounds__(256, 2)
void bgemm_kernel(const __nv_bfloat16* __restrict__ Ah1,
                  const __nv_bfloat16* __restrict__ Am1, int K1,
                  const __nv_bfloat16* __restrict__ Ah2,
                  const __nv_bfloat16* __restrict__ Am2, int K2,
                  const __nv_bfloat16* __restrict__ Bh,
                  const __nv_bfloat16* __restrict__ Bm,
                  const float* __restrict__ bias,
                  __nv_bfloat16* __restrict__ outHi,
                  __nv_bfloat16* __restrict__ outMid,
                  int N, long sA, long sB, long sC,
                  int act, const float* __restrict__ alpha)
{
    extern __shared__ __align__(1024) char smem[];
    const uint32_t sb = smem_u32(smem);
    const int K  = K1 + K2;
    const int nc = K >> 5;
    const int bz = blockIdx.z;
    const __nv_bfloat16* Ah1b = Ah1 + (size_t)bz * sA;
    const __nv_bfloat16* Am1b = Am1 + (size_t)bz * sA;
    const __nv_bfloat16* Bhb  = Bh + (size_t)bz * sB;
    const __nv_bfloat16* Bmb  = Bm + (size_t)bz * sB;
    __nv_bfloat16* oHi = outHi + (size_t)bz * sC;
    __nv_bfloat16* oMi = outMid + (size_t)bz * sC;

    const int tid  = threadIdx.x;
    const int wid  = tid >> 5;
    const int lane = tid & 31;
    const int warpM = wid >> 1;
    const int warpN = wid & 1;
    const int lr = lane >> 2, lc = lane & 3;

    const int rowBase = blockIdx.y * 128;
    const int colBase = blockIdx.x * 128;

    const uint32_t aLane = (uint32_t)((lane & 15) * A_STRIDE_B + (lane >> 4) * 16);
    const uint32_t bLane = (uint32_t)((((lane & 7) + ((lane >> 3) & 1) * 8)) * B_STRIDE_B
                                      + ((lane >> 4) & 1) * 16);

    float acc[2][8][4];
#pragma unroll
    for (int mi = 0; mi < 2; mi++)
#pragma unroll
        for (int ni = 0; ni < 8; ni++)
#pragma unroll
            for (int j = 0; j < 4; j++) acc[mi][ni][j] = 0.f;

    auto fetch = [&](int ch) {
        const uint32_t stb = sb + (uint32_t)(ch % NST) * STG_BYTES;
        const int kc = ch << 5;
        const __nv_bfloat16 *Aph, *Apm; int lda, ko;
        if (kc < K1) { Aph = Ah1b; Apm = Am1b; lda = K1; ko = kc; }
        else         { Aph = Ah2;  Apm = Am2;  lda = K2; ko = kc - K1; }
#pragma unroll
        for (int i = 0; i < 2; i++) {
            int f = 2 * tid + i;
            int m = f >> 2, q = f & 3;                  // A: 128 rows x 4 x 16B
            size_t so = (size_t)(rowBase + m) * lda + ko + q * 8;
            uint32_t doff = (uint32_t)(m * A_STRIDE_B + q * 16);
            cpa16(stb + A_HI_S  + doff, Aph + so);
            cpa16(stb + A_MID_S + doff, Apm + so);
        }
#pragma unroll
        for (int i = 0; i < 2; i++) {
            int f = 2 * tid + i;
            int k = f >> 4, q = f & 15;                 // B: 32 rows x 16 x 16B
            size_t so = (size_t)(kc + k) * N + colBase + q * 8;
            uint32_t doff = (uint32_t)(k * B_STRIDE_B + q * 16);
            cpa16(stb + B_HI_S  + doff, Bhb + so);
            cpa16(stb + B_MID_S + doff, Bmb + so);
        }
    };

    fetch(0); CPA_COMMIT();
    fetch(1); CPA_COMMIT();

    for (int ch = 0; ch < nc; ++ch) {
        CPA_WAIT1();
        __syncthreads();

        const uint32_t stb = sb + (uint32_t)(ch % NST) * STG_BYTES;
        const uint32_t aHiB = stb + A_HI_S  + (uint32_t)(warpM * 32) * A_STRIDE_B + aLane;
        const uint32_t aMiB = stb + A_MID_S + (uint32_t)(warpM * 32) * A_STRIDE_B + aLane;
        const uint32_t bHiB = stb + B_HI_S  + (uint32_t)(warpN * 128) + bLane;
        const uint32_t bMiB = stb + B_MID_S + (uint32_t)(warpN * 128) + bLane;

#pragma unroll
        for (int ks = 0; ks < 2; ks++) {
            uint32_t ah[2][4], am[2][4];
#pragma unroll
            for (int mi = 0; mi < 2; mi++) {
                ldsm_x4(ah[mi], aHiB + mi * 16 * A_STRIDE_B + ks * 32);
                ldsm_x4(am[mi], aMiB + mi * 16 * A_STRIDE_B + ks * 32);
            }
#pragma unroll
            for (int g = 0; g < 4; g++) {
                uint32_t bh[4], bm[4];
                ldsm_x4_trans(bh, bHiB + ks * 16 * B_STRIDE_B + g * 32);
                ldsm_x4_trans(bm, bMiB + ks * 16 * B_STRIDE_B + g * 32);
#pragma unroll
                for (int sub = 0; sub < 2; sub++) {
                    const uint32_t b0h = bh[sub * 2], b1h = bh[sub * 2 + 1];
                    const uint32_t b0m = bm[sub * 2], b1m = bm[sub * 2 + 1];
                    const int ni = g * 2 + sub;
#pragma unroll
                    for (int mi = 0; mi < 2; mi++) {
                        mma_bf16(acc[mi][ni], ah[mi], b0h, b1h);
                        mma_bf16(acc[mi][ni], am[mi], b0h, b1h);
                        mma_bf16(acc[mi][ni], ah[mi], b0m, b1m);
                    }
                }
            }
        }

        if (ch + 2 < nc) fetch(ch + 2);
        CPA_COMMIT();
    }

    // Epilogue: bias + act, write bf16 hi + mid residual
#pragma unroll
    for (int mi = 0; mi < 2; mi++) {
#pragma unroll
        for (int ni = 0; ni < 8; ni++) {
#pragma unroll
            for (int half = 0; half < 2; half++) {
                int r = rowBase + warpM * 32 + mi * 16 + lr + half * 8;
                int c = colBase + warpN * 64 + ni * 8 + lc * 2;
                float v0 = acc[mi][ni][half * 2 + 0];
                float v1 = acc[mi][ni][half * 2 + 1];
                if (bias) { v0 += bias[c]; v1 += bias[c + 1]; }
                if (act == 1) {
                    v0 = fmaxf(v0, 0.f); v1 = fmaxf(v1, 0.f);
                } else if (act == 2) {
                    v0 = v0 > 0.f ? v0 : alpha[c] * v0;
                    v1 = v1 > 0.f ? v1 : alpha[c + 1] * v1;
                }
                __nv_bfloat162 h2 = __floats2bfloat162_rn(v0, v1);
                float2 hf = __bfloat1622float2(h2);
                __nv_bfloat162 m2 = __floats2bfloat162_rn(v0 - hf.x, v1 - hf.y);
                size_t o = (size_t)r * N + c;
                *reinterpret_cast<__nv_bfloat162*>(oHi + o) = h2;
                *reinterpret_cast<__nv_bfloat162*>(oMi + o) = m2;
            }
        }
    }
}

// pred[M,2] = H[M,K] @ W[K,2] + b[2]; H given as bf16 hi+mid (warp per row)
__global__ void final_head_kernel(const __nv_bfloat16* __restrict__ Hh,
                                  const __nv_bfloat16* __restrict__ Hm,
                                  const float* __restrict__ W,
                                  const float* __restrict__ b,
                                  float* __restrict__ out,
                                  int M, int K)
{
    __shared__ float w0[256], w1[256];
    const int tid = threadIdx.x;
    for (int i = tid; i < K; i += blockDim.x) {
        w0[i] = W[i * 2 + 0];
        w1[i] = W[i * 2 + 1];
    }
    __syncthreads();

    const int warp = tid >> 5;
    const int lane = tid & 31;
    const int row  = blockIdx.x * (blockDim.x >> 5) + warp;
    if (row >= M) return;

    const __nv_bfloat16* hh = Hh + (size_t)row * K;
    const __nv_bfloat16* hm = Hm + (size_t)row * K;
    float s0 = 0.f, s1 = 0.f;
    for (int c = lane; c < K; c += 32) {
        float v = __bfloat162float(hh[c]) + __bfloat162float(hm[c]);
        s0 += v * w0[c];
        s1 += v * w1[c];
    }
#pragma unroll
    for (int o = 16; o; o >>= 1) {
        s0 += __shfl_xor_sync(0xFFFFFFFFu, s0, o);
        s1 += __shfl_xor_sync(0xFFFFFFFFu, s1, o);
    }
    if (lane == 0) {
        out[row * 2 + 0] = s0 + b[0];
        out[row * 2 + 1] = s1 + b[1];
    }
}

extern "C" void kernel_launch(void* const* d_in, const int* in_sizes, int n_in,
                              void* d_out, int out_size)
{
    const float* x   = (const float*)d_in[0];
    const float* adj = (const float*)d_in[1];
    const float* W1  = (const float*)d_in[2];
    const float* b1  = (const float*)d_in[3];
    const float* W2  = (const float*)d_in[4];
    const float* b2  = (const float*)d_in[5];
    const float* W3  = (const float*)d_in[6];
    const float* b3  = (const float*)d_in[7];
    const float* W4  = (const float*)d_in[8];
    const float* b4  = (const float*)d_in[9];
    const float* cW1 = (const float*)d_in[10];
    const float* cb1 = (const float*)d_in[11];
    const float* alp = (const float*)d_in[12];
    const float* cW2 = (const float*)d_in[13];
    const float* cb2 = (const float*)d_in[14];
    float* out = (float*)d_out;

    __nv_bfloat16 *adjH, *adjM, *xH, *xM, *hAH, *hAM, *hBH, *hBM, *agH, *agM, *wH, *wM;
    cudaGetSymbolAddress((void**)&adjH, s_adj_h); cudaGetSymbolAddress((void**)&adjM, s_adj_m);
    cudaGetSymbolAddress((void**)&xH,   s_x_h);   cudaGetSymbolAddress((void**)&xM,   s_x_m);
    cudaGetSymbolAddress((void**)&hAH,  s_hA_h);  cudaGetSymbolAddress((void**)&hAM,  s_hA_m);
    cudaGetSymbolAddress((void**)&hBH,  s_hB_h);  cudaGetSymbolAddress((void**)&hBM,  s_hB_m);
    cudaGetSymbolAddress((void**)&agH,  s_ag_h);  cudaGetSymbolAddress((void**)&agM,  s_ag_m);
    cudaGetSymbolAddress((void**)&wH,   s_w_h);   cudaGetSymbolAddress((void**)&wM,   s_w_m);

    static bool attrSet = false;
    if (!attrSet) {
        cudaFuncSetAttribute(bgemm_kernel, cudaFuncAttributeMaxDynamicSharedMemorySize,
                             SMEM_BYTES);
        attrSet = true;
    }

    const int Bb = 32, Nn = 1024, D = 256, Hd = 512, Hh = 256;
    const int MB = Bb * Nn;  // 32768

    auto split = [&](const float* src, __nv_bfloat16* hi, __nv_bfloat16* mid, int n) {
        split_kernel<<<n / 1024, 256>>>(src, hi, mid, n);
    };

    // Weight offsets inside wH/wM
    const size_t oW1 = 0, oW2 = 262144, oW3 = 786432, oW4 = 1048576, oC1 = 1179648;

    split(adj, adjH, adjM, Bb * Nn * Nn);
    split(x,   xH,   xM,   Bb * Nn * D);
    split(W1,  wH + oW1, wM + oW1, 2 * D * Hd);
    split(W2,  wH + oW2, wM + oW2, 2 * Hd * Hd);
    split(W3,  wH + oW3, wM + oW3, 2 * Hd * Hh);
    split(W4,  wH + oW4, wM + oW4, 2 * Hh * Hh);
    split(cW1, wH + oC1, wM + oC1, Hh * Hh);

    auto gemm = [&](const __nv_bfloat16* Ah1, const __nv_bfloat16* Am1, int K1,
                    const __nv_bfloat16* Ah2, const __nv_bfloat16* Am2, int K2,
                    const __nv_bfloat16* Bh, const __nv_bfloat16* Bm,
                    const float* bias, __nv_bfloat16* oH, __nv_bfloat16* oM,
                    int M, int N, int batch, long sA, long sB, long sC,
                    int act, const float* alpha) {
        dim3 g(N / 128, M / 128, batch);
        bgemm_kernel<<<g, 256, SMEM_BYTES>>>(Ah1, Am1, K1, Ah2, Am2, K2, Bh, Bm,
                                             bias, oH, oM, N, sA, sB, sC, act, alpha);
    };

    // ---- Layer 1: agg = adj @ x ; h1 = relu([x|agg] W1 + b1) -> hA ----
    gemm(adjH, adjM, Nn, nullptr, nullptr, 0, xH, xM, nullptr, agH, agM,
         Nn, D, Bb, (long)Nn * Nn, (long)Nn * D, (long)Nn * D, 0, nullptr);
    gemm(xH, xM, D, agH, agM, D, wH + oW1, wM + oW1, b1, hAH, hAM,
         MB, Hd, 1, 0, 0, 0, 1, nullptr);

    // ---- Layer 2: agg = adj @ hA ; h2 = relu([hA|agg] W2 + b2) -> hB ----
    gemm(adjH, adjM, Nn, nullptr, nullptr, 0, hAH, hAM, nullptr, agH, agM,
         Nn, Hd, Bb, (long)Nn * Nn, (long)Nn * Hd, (long)Nn * Hd, 0, nullptr);
    gemm(hAH, hAM, Hd, agH, agM, Hd, wH + oW2, wM + oW2, b2, hBH, hBM,
         MB, Hd, 1, 0, 0, 0, 1, nullptr);

    // ---- Layer 3: agg = adj @ hB ; h3 = relu([hB|agg] W3 + b3) -> hA ----
    gemm(adjH, adjM, Nn, nullptr, nullptr, 0, hBH, hBM, nullptr, agH, agM,
         Nn, Hd, Bb, (long)Nn * Nn, (long)Nn * Hd, (long)Nn * Hd, 0, nullptr);
    gemm(hBH, hBM, Hd, agH, agM, Hd, wH + oW3, wM + oW3, b3, hAH, hAM,
         MB, Hh, 1, 0, 0, 0, 1, nullptr);

    // ---- Layer 4: agg = adj @ hA ; h4 = relu([hA|agg] W4 + b4) -> hB ----
    gemm(adjH, adjM, Nn, nullptr, nullptr, 0, hAH, hAM, nullptr, agH, agM,
         Nn, Hh, Bb, (long)Nn * Nn, (long)Nn * Hh, (long)Nn * Hh, 0, nullptr);
    gemm(hAH, hAM, Hh, agH, agM, Hh, wH + oW4, wM + oW4, b4, hBH, hBM,
         MB, Hh, 1, 0, 0, 0, 1, nullptr);

    // ---- Classifier: c1 = prelu(hB @ cW1 + cb1) -> hA ; pred -> out ----
    gemm(hBH, hBM, Hh, nullptr, nullptr, 0, wH + oC1, wM + oC1, cb1, hAH, hAM,
         MB, Hh, 1, 0, 0, 0, 2, alp);
    final_head_kernel<<<MB / 8, 256>>>(hAH, hAM, cW2, cb2, out, MB, Hh);
}

// round 13
// speedup vs baseline: 2.9120x; 1.0406x over previous
#include <cuda_runtime.h>
#include <cuda_bf16.h>
#include <cstdint>
#include <cstddef>

// ---------------- bf16 scratch (no allocs allowed) ----------------
__device__ __nv_bfloat16 s_adj_h[32u*1024u*1024u];
__device__ __nv_bfloat16 s_adj_m[32u*1024u*1024u];
__device__ __nv_bfloat16 s_x_h[32u*1024u*256u];
__device__ __nv_bfloat16 s_x_m[32u*1024u*256u];
__device__ __nv_bfloat16 s_hA_h[32u*1024u*512u];
__device__ __nv_bfloat16 s_hA_m[32u*1024u*512u];
__device__ __nv_bfloat16 s_hB_h[32u*1024u*512u];
__device__ __nv_bfloat16 s_hB_m[32u*1024u*512u];
__device__ __nv_bfloat16 s_ag_h[32u*1024u*512u];
__device__ __nv_bfloat16 s_ag_m[32u*1024u*512u];
__device__ __nv_bfloat16 s_w_h[2u<<20];
__device__ __nv_bfloat16 s_w_m[2u<<20];

// ---------------- smem geometry (bytes) ----------------
// A: [128 m][32 k] bf16, row stride 80B. B: [32 k][128 n] bf16, row stride 272B.
#define A_STRIDE_B 80
#define B_STRIDE_B 272
#define A_HI_S  0
#define A_MID_S 10240
#define B_HI_S  20480
#define B_MID_S 29184
#define STG_BYTES 37888
#define NST 3
#define SMEM_BYTES (NST * STG_BYTES)   // 113664

__device__ __forceinline__ uint32_t smem_u32(const void* p) {
    uint32_t a;
    asm("{ .reg .u64 t; cvta.to.shared.u64 t, %1; cvt.u32.u64 %0, t; }" : "=r"(a) : "l"(p));
    return a;
}
__device__ __forceinline__ void cpa16(uint32_t dst, const void* src) {
    asm volatile("cp.async.cg.shared.global [%0], [%1], 16;" :: "r"(dst), "l"(src));
}
#define CPA_COMMIT() asm volatile("cp.async.commit_group;" ::: "memory")
#define CPA_WAIT1()  asm volatile("cp.async.wait_group 1;" ::: "memory")

__device__ __forceinline__ void ldsm_x4(uint32_t r[4], uint32_t addr) {
    asm volatile("ldmatrix.sync.aligned.m8n8.x4.shared.b16 {%0,%1,%2,%3}, [%4];"
                 : "=r"(r[0]), "=r"(r[1]), "=r"(r[2]), "=r"(r[3]) : "r"(addr));
}
__device__ __forceinline__ void ldsm_x4_trans(uint32_t r[4], uint32_t addr) {
    asm volatile("ldmatrix.sync.aligned.m8n8.x4.trans.shared.b16 {%0,%1,%2,%3}, [%4];"
                 : "=r"(r[0]), "=r"(r[1]), "=r"(r[2]), "=r"(r[3]) : "r"(addr));
}
__device__ __forceinline__ void mma_bf16(float c[4], const uint32_t a[4],
                                         uint32_t b0, uint32_t b1) {
    asm volatile(
        "mma.sync.aligned.m16n8k16.row.col.f32.bf16.bf16.f32 "
        "{%0,%1,%2,%3}, {%4,%5,%6,%7}, {%8,%9}, {%0,%1,%2,%3};"
        : "+f"(c[0]), "+f"(c[1]), "+f"(c[2]), "+f"(c[3])
        : "r"(a[0]), "r"(a[1]), "r"(a[2]), "r"(a[3]), "r"(b0), "r"(b1));
}

// ---------------------------------------------------------------------------
// Split fp32 -> bf16 hi + bf16 mid (residual). n divisible by 1024.
// ---------------------------------------------------------------------------
__global__ void split_kernel(const float* __restrict__ in,
                             __nv_bfloat16* __restrict__ hi,
                             __nv_bfloat16* __restrict__ mid, int n)
{
    int i = blockIdx.x * blockDim.x + threadIdx.x;
    float4 v = reinterpret_cast<const float4*>(in)[i];
    __nv_bfloat162 h01 = __floats2bfloat162_rn(v.x, v.y);
    __nv_bfloat162 h23 = __floats2bfloat162_rn(v.z, v.w);
    float2 f01 = __bfloat1622float2(h01);
    float2 f23 = __bfloat1622float2(h23);
    __nv_bfloat162 m01 = __floats2bfloat162_rn(v.x - f01.x, v.y - f01.y);
    __nv_bfloat162 m23 = __floats2bfloat162_rn(v.z - f23.x, v.w - f23.y);
    reinterpret_cast<__nv_bfloat162*>(hi)[2*i]   = h01;
    reinterpret_cast<__nv_bfloat162*>(hi)[2*i+1] = h23;
    reinterpret_cast<__nv_bfloat162*>(mid)[2*i]   = m01;
    reinterpret_cast<__nv_bfloat162*>(mid)[2*i+1] = m23;
}

// ---------------------------------------------------------------------------
// C = act([A1|A2] @ B + bias), bf16x3 on mma.sync, cp.async 3-stage pipeline.
// 128 threads / 4 warps; each warp owns a 64x64 subtile (CTA tile 128x128).
// All matrix operands pre-split bf16 (hi/mid). Output written as bf16 hi/mid.
// ---------------------------------------------------------------------------
__global__ __launch_bounds__(128, 2)
void bgemm_kernel(const __nv_bfloat16* __restrict__ Ah1,
                  const __nv_bfloat16* __restrict__ Am1, int K1,
                  const __nv_bfloat16* __restrict__ Ah2,
                  const __nv_bfloat16* __restrict__ Am2, int K2,
                  const __nv_bfloat16* __restrict__ Bh,
                  const __nv_bfloat16* __restrict__ Bm,
                  const float* __restrict__ bias,
                  __nv_bfloat16* __restrict__ outHi,
                  __nv_bfloat16* __restrict__ outMid,
                  int N, long sA, long sB, long sC,
                  int act, const float* __restrict__ alpha)
{
    extern __shared__ __align__(1024) char smem[];
    const uint32_t sb = smem_u32(smem);
    const int K  = K1 + K2;
    const int nc = K >> 5;
    const int bz = blockIdx.z;
    const __nv_bfloat16* Ah1b = Ah1 + (size_t)bz * sA;
    const __nv_bfloat16* Am1b = Am1 + (size_t)bz * sA;
    const __nv_bfloat16* Bhb  = Bh + (size_t)bz * sB;
    const __nv_bfloat16* Bmb  = Bm + (size_t)bz * sB;
    __nv_bfloat16* oHi = outHi + (size_t)bz * sC;
    __nv_bfloat16* oMi = outMid + (size_t)bz * sC;

    const int tid  = threadIdx.x;
    const int wid  = tid >> 5;
    const int lane = tid & 31;
    const int warpM = wid >> 1;          // 0..1 -> 64 rows
    const int warpN = wid & 1;           // 0..1 -> 64 cols
    const int lr = lane >> 2, lc = lane & 3;

    const int rowBase = blockIdx.y * 128;
    const int colBase = blockIdx.x * 128;

    const uint32_t aLane = (uint32_t)((lane & 15) * A_STRIDE_B + (lane >> 4) * 16);
    const uint32_t bLane = (uint32_t)((((lane & 7) + ((lane >> 3) & 1) * 8)) * B_STRIDE_B
                                      + ((lane >> 4) & 1) * 16);

    float acc[4][8][4];
#pragma unroll
    for (int mi = 0; mi < 4; mi++)
#pragma unroll
        for (int ni = 0; ni < 8; ni++)
#pragma unroll
            for (int j = 0; j < 4; j++) acc[mi][ni][j] = 0.f;

    auto fetch = [&](int ch) {
        const uint32_t stb = sb + (uint32_t)(ch % NST) * STG_BYTES;
        const int kc = ch << 5;
        const __nv_bfloat16 *Aph, *Apm; int lda, ko;
        if (kc < K1) { Aph = Ah1b; Apm = Am1b; lda = K1; ko = kc; }
        else         { Aph = Ah2;  Apm = Am2;  lda = K2; ko = kc - K1; }
#pragma unroll
        for (int i = 0; i < 4; i++) {
            int f = tid + (i << 7);                    // A: 128 rows x 4 x 16B
            int m = f >> 2, q = f & 3;
            size_t so = (size_t)(rowBase + m) * lda + ko + q * 8;
            uint32_t doff = (uint32_t)(m * A_STRIDE_B + q * 16);
            cpa16(stb + A_HI_S  + doff, Aph + so);
            cpa16(stb + A_MID_S + doff, Apm + so);
        }
#pragma unroll
        for (int i = 0; i < 4; i++) {
            int f = tid + (i << 7);                    // B: 32 rows x 16 x 16B
            int k = f >> 4, q = f & 15;
            size_t so = (size_t)(kc + k) * N + colBase + q * 8;
            uint32_t doff = (uint32_t)(k * B_STRIDE_B + q * 16);
            cpa16(stb + B_HI_S  + doff, Bhb + so);
            cpa16(stb + B_MID_S + doff, Bmb + so);
        }
    };

    fetch(0); CPA_COMMIT();
    fetch(1); CPA_COMMIT();

    for (int ch = 0; ch < nc; ++ch) {
        CPA_WAIT1();
        __syncthreads();

        const uint32_t stb = sb + (uint32_t)(ch % NST) * STG_BYTES;
        const uint32_t aHiB = stb + A_HI_S  + (uint32_t)(warpM * 64) * A_STRIDE_B + aLane;
        const uint32_t aMiB = stb + A_MID_S + (uint32_t)(warpM * 64) * A_STRIDE_B + aLane;
        const uint32_t bHiB = stb + B_HI_S  + (uint32_t)(warpN * 128) + bLane;
        const uint32_t bMiB = stb + B_MID_S + (uint32_t)(warpN * 128) + bLane;

#pragma unroll
        for (int ks = 0; ks < 2; ks++) {
            uint32_t ah[4][4], am[4][4];
#pragma unroll
            for (int mi = 0; mi < 4; mi++) {
                ldsm_x4(ah[mi], aHiB + mi * 16 * A_STRIDE_B + ks * 32);
                ldsm_x4(am[mi], aMiB + mi * 16 * A_STRIDE_B + ks * 32);
            }
#pragma unroll
            for (int g = 0; g < 4; g++) {
                uint32_t bh[4], bm[4];
                ldsm_x4_trans(bh, bHiB + ks * 16 * B_STRIDE_B + g * 32);
                ldsm_x4_trans(bm, bMiB + ks * 16 * B_STRIDE_B + g * 32);
#pragma unroll
                for (int sub = 0; sub < 2; sub++) {
                    const uint32_t b0h = bh[sub * 2], b1h = bh[sub * 2 + 1];
                    const uint32_t b0m = bm[sub * 2], b1m = bm[sub * 2 + 1];
                    const int ni = g * 2 + sub;
#pragma unroll
                    for (int mi = 0; mi < 4; mi++) {
                        mma_bf16(acc[mi][ni], ah[mi], b0h, b1h);
                        mma_bf16(acc[mi][ni], am[mi], b0h, b1h);
                        mma_bf16(acc[mi][ni], ah[mi], b0m, b1m);
                    }
                }
            }
        }

        if (ch + 2 < nc) fetch(ch + 2);
        CPA_COMMIT();
    }

    // Epilogue: bias + act, write bf16 hi + mid residual
#pragma unroll
    for (int mi = 0; mi < 4; mi++) {
#pragma unroll
        for (int ni = 0; ni < 8; ni++) {
#pragma unroll
            for (int half = 0; half < 2; half++) {
                int r = rowBase + warpM * 64 + mi * 16 + lr + half * 8;
                int c = colBase + warpN * 64 + ni * 8 + lc * 2;
                float v0 = acc[mi][ni][half * 2 + 0];
                float v1 = acc[mi][ni][half * 2 + 1];
                if (bias) { v0 += bias[c]; v1 += bias[c + 1]; }
                if (act == 1) {
                    v0 = fmaxf(v0, 0.f); v1 = fmaxf(v1, 0.f);
                } else if (act == 2) {
                    v0 = v0 > 0.f ? v0 : alpha[c] * v0;
                    v1 = v1 > 0.f ? v1 : alpha[c + 1] * v1;
                }
                __nv_bfloat162 h2 = __floats2bfloat162_rn(v0, v1);
                float2 hf = __bfloat1622float2(h2);
                __nv_bfloat162 m2 = __floats2bfloat162_rn(v0 - hf.x, v1 - hf.y);
                size_t o = (size_t)r * N + c;
                *reinterpret_cast<__nv_bfloat162*>(oHi + o) = h2;
                *reinterpret_cast<__nv_bfloat162*>(oMi + o) = m2;
            }
        }
    }
}

// pred[M,2] = H[M,K] @ W[K,2] + b[2]; H given as bf16 hi+mid (warp per row)
__global__ void final_head_kernel(const __nv_bfloat16* __restrict__ Hh,
                                  const __nv_bfloat16* __restrict__ Hm,
                                  const float* __restrict__ W,
                                  const float* __restrict__ b,
                                  float* __restrict__ out,
                                  int M, int K)
{
    __shared__ float w0[256], w1[256];
    const int tid = threadIdx.x;
    for (int i = tid; i < K; i += blockDim.x) {
        w0[i] = W[i * 2 + 0];
        w1[i] = W[i * 2 + 1];
    }
    __syncthreads();

    const int warp = tid >> 5;
    const int lane = tid & 31;
    const int row  = blockIdx.x * (blockDim.x >> 5) + warp;
    if (row >= M) return;

    const __nv_bfloat16* hh = Hh + (size_t)row * K;
    const __nv_bfloat16* hm = Hm + (size_t)row * K;
    float s0 = 0.f, s1 = 0.f;
    for (int c = lane; c < K; c += 32) {
        float v = __bfloat162float(hh[c]) + __bfloat162float(hm[c]);
        s0 += v * w0[c];
        s1 += v * w1[c];
    }
#pragma unroll
    for (int o = 16; o; o >>= 1) {
        s0 += __shfl_xor_sync(0xFFFFFFFFu, s0, o);
        s1 += __shfl_xor_sync(0xFFFFFFFFu, s1, o);
    }
    if (lane == 0) {
        out[row * 2 + 0] = s0 + b[0];
        out[row * 2 + 1] = s1 + b[1];
    }
}

extern "C" void kernel_launch(void* const* d_in, const int* in_sizes, int n_in,
                              void* d_out, int out_size)
{
    const float* x   = (const float*)d_in[0];
    const float* adj = (const float*)d_in[1];
    const float* W1  = (const float*)d_in[2];
    const float* b1  = (const float*)d_in[3];
    const float* W2  = (const float*)d_in[4];
    const float* b2  = (const float*)d_in[5];
    const float* W3  = (const float*)d_in[6];
    const float* b3  = (const float*)d_in[7];
    const float* W4  = (const float*)d_in[8];
    const float* b4  = (const float*)d_in[9];
    const float* cW1 = (const float*)d_in[10];
    const float* cb1 = (const float*)d_in[11];
    const float* alp = (const float*)d_in[12];
    const float* cW2 = (const float*)d_in[13];
    const float* cb2 = (const float*)d_in[14];
    float* out = (float*)d_out;

    __nv_bfloat16 *adjH, *adjM, *xH, *xM, *hAH, *hAM, *hBH, *hBM, *agH, *agM, *wH, *wM;
    cudaGetSymbolAddress((void**)&adjH, s_adj_h); cudaGetSymbolAddress((void**)&adjM, s_adj_m);
    cudaGetSymbolAddress((void**)&xH,   s_x_h);   cudaGetSymbolAddress((void**)&xM,   s_x_m);
    cudaGetSymbolAddress((void**)&hAH,  s_hA_h);  cudaGetSymbolAddress((void**)&hAM,  s_hA_m);
    cudaGetSymbolAddress((void**)&hBH,  s_hB_h);  cudaGetSymbolAddress((void**)&hBM,  s_hB_m);
    cudaGetSymbolAddress((void**)&agH,  s_ag_h);  cudaGetSymbolAddress((void**)&agM,  s_ag_m);
    cudaGetSymbolAddress((void**)&wH,   s_w_h);   cudaGetSymbolAddress((void**)&wM,   s_w_m);

    static bool attrSet = false;
    if (!attrSet) {
        cudaFuncSetAttribute(bgemm_kernel, cudaFuncAttributeMaxDynamicSharedMemorySize,
                             SMEM_BYTES);
        attrSet = true;
    }

    const int Bb = 32, Nn = 1024, D = 256, Hd = 512, Hh = 256;
    const int MB = Bb * Nn;  // 32768

    auto split = [&](const float* src, __nv_bfloat16* hi, __nv_bfloat16* mid, int n) {
        split_kernel<<<n / 1024, 256>>>(src, hi, mid, n);
    };

    // Weight offsets inside wH/wM
    const size_t oW1 = 0, oW2 = 262144, oW3 = 786432, oW4 = 1048576, oC1 = 1179648;

    split(adj, adjH, adjM, Bb * Nn * Nn);
    split(x,   xH,   xM,   Bb * Nn * D);
    split(W1,  wH + oW1, wM + oW1, 2 * D * Hd);
    split(W2,  wH + oW2, wM + oW2, 2 * Hd * Hd);
    split(W3,  wH + oW3, wM + oW3, 2 * Hd * Hh);
    split(W4,  wH + oW4, wM + oW4, 2 * Hh * Hh);
    split(cW1, wH + oC1, wM + oC1, Hh * Hh);

    auto gemm = [&](const __nv_bfloat16* Ah1, const __nv_bfloat16* Am1, int K1,
                    const __nv_bfloat16* Ah2, const __nv_bfloat16* Am2, int K2,
                    const __nv_bfloat16* Bh, const __nv_bfloat16* Bm,
                    const float* bias, __nv_bfloat16* oH, __nv_bfloat16* oM,
                    int M, int N, int batch, long sA, long sB, long sC,
                    int act, const float* alpha) {
        dim3 g(N / 128, M / 128, batch);
        bgemm_kernel<<<g, 128, SMEM_BYTES>>>(Ah1, Am1, K1, Ah2, Am2, K2, Bh, Bm,
                                             bias, oH, oM, N, sA, sB, sC, act, alpha);
    };

    // ---- Layer 1: agg = adj @ x ; h1 = relu([x|agg] W1 + b1) -> hA ----
    gemm(adjH, adjM, Nn, nullptr, nullptr, 0, xH, xM, nullptr, agH, agM,
         Nn, D, Bb, (long)Nn * Nn, (long)Nn * D, (long)Nn * D, 0, nullptr);
    gemm(xH, xM, D, agH, agM, D, wH + oW1, wM + oW1, b1, hAH, hAM,
         MB, Hd, 1, 0, 0, 0, 1, nullptr);

    // ---- Layer 2: agg = adj @ hA ; h2 = relu([hA|agg] W2 + b2) -> hB ----
    gemm(adjH, adjM, Nn, nullptr, nullptr, 0, hAH, hAM, nullptr, agH, agM,
         Nn, Hd, Bb, (long)Nn * Nn, (long)Nn * Hd, (long)Nn * Hd, 0, nullptr);
    gemm(hAH, hAM, Hd, agH, agM, Hd, wH + oW2, wM + oW2, b2, hBH, hBM,
         MB, Hd, 1, 0, 0, 0, 1, nullptr);

    // ---- Layer 3: agg = adj @ hB ; h3 = relu([hB|agg] W3 + b3) -> hA ----
    gemm(adjH, adjM, Nn, nullptr, nullptr, 0, hBH, hBM, nullptr, agH, agM,
         Nn, Hd, Bb, (long)Nn * Nn, (long)Nn * Hd, (long)Nn * Hd, 0, nullptr);
    gemm(hBH, hBM, Hd, agH, agM, Hd, wH + oW3, wM + oW3, b3, hAH, hAM,
         MB, Hh, 1, 0, 0, 0, 1, nullptr);

    // ---- Layer 4: agg = adj @ hA ; h4 = relu([hA|agg] W4 + b4) -> hB ----
    gemm(adjH, adjM, Nn, nullptr, nullptr, 0, hAH, hAM, nullptr, agH, agM,
         Nn, Hh, Bb, (long)Nn * Nn, (long)Nn * Hh, (long)Nn * Hh, 0, nullptr);
    gemm(hAH, hAM, Hh, agH, agM, Hh, wH + oW4, wM + oW4, b4, hBH, hBM,
         MB, Hh, 1, 0, 0, 0, 1, nullptr);

    // ---- Classifier: c1 = prelu(hB @ cW1 + cb1) -> hA ; pred -> out ----
    gemm(hBH, hBM, Hh, nullptr, nullptr, 0, wH + oC1, wM + oC1, cb1, hAH, hAM,
         MB, Hh, 1, 0, 0, 0, 2, alp);
    final_head_kernel<<<MB / 8, 256>>>(hAH, hAM, cW2, cb2, out, MB, Hh);
}

// round 14
// speedup vs baseline: 2.9366x; 1.0084x over previous
#include <cuda_runtime.h>
#include <cuda_bf16.h>
#include <cstdint>
#include <cstddef>

// ---------------- bf16 scratch (no allocs allowed) ----------------
__device__ __nv_bfloat16 s_adj_h[32u*1024u*1024u];
__device__ __nv_bfloat16 s_adj_m[32u*1024u*1024u];
__device__ __nv_bfloat16 s_x_h[32u*1024u*256u];
__device__ __nv_bfloat16 s_x_m[32u*1024u*256u];
__device__ __nv_bfloat16 s_hA_h[32u*1024u*512u];
__device__ __nv_bfloat16 s_hA_m[32u*1024u*512u];
__device__ __nv_bfloat16 s_hB_h[32u*1024u*512u];
__device__ __nv_bfloat16 s_hB_m[32u*1024u*512u];
__device__ __nv_bfloat16 s_ag_h[32u*1024u*512u];
__device__ __nv_bfloat16 s_ag_m[32u*1024u*512u];
__device__ __nv_bfloat16 s_w_h[2u<<20];
__device__ __nv_bfloat16 s_w_m[2u<<20];

// ---------------- smem geometry (bytes) ----------------
#define A_STRIDE_B 80
#define B_STRIDE_B 272
#define A_HI_S  0
#define A_MID_S 10240
#define B_HI_S  20480
#define B_MID_S 29184
#define STG_BYTES 37888
#define NST 3
#define SMEM_BYTES (NST * STG_BYTES)   // 113664

__device__ __forceinline__ uint32_t smem_u32(const void* p) {
    uint32_t a;
    asm("{ .reg .u64 t; cvta.to.shared.u64 t, %1; cvt.u32.u64 %0, t; }" : "=r"(a) : "l"(p));
    return a;
}
__device__ __forceinline__ void cpa16(uint32_t dst, const void* src) {
    asm volatile("cp.async.cg.shared.global [%0], [%1], 16;" :: "r"(dst), "l"(src));
}
#define CPA_COMMIT() asm volatile("cp.async.commit_group;" ::: "memory")
#define CPA_WAIT1()  asm volatile("cp.async.wait_group 1;" ::: "memory")

__device__ __forceinline__ void ldsm_x4(uint32_t r[4], uint32_t addr) {
    asm volatile("ldmatrix.sync.aligned.m8n8.x4.shared.b16 {%0,%1,%2,%3}, [%4];"
                 : "=r"(r[0]), "=r"(r[1]), "=r"(r[2]), "=r"(r[3]) : "r"(addr));
}
__device__ __forceinline__ void ldsm_x4_trans(uint32_t r[4], uint32_t addr) {
    asm volatile("ldmatrix.sync.aligned.m8n8.x4.trans.shared.b16 {%0,%1,%2,%3}, [%4];"
                 : "=r"(r[0]), "=r"(r[1]), "=r"(r[2]), "=r"(r[3]) : "r"(addr));
}
__device__ __forceinline__ void mma_bf16(float c[4], const uint32_t a[4],
                                         uint32_t b0, uint32_t b1) {
    asm volatile(
        "mma.sync.aligned.m16n8k16.row.col.f32.bf16.bf16.f32 "
        "{%0,%1,%2,%3}, {%4,%5,%6,%7}, {%8,%9}, {%0,%1,%2,%3};"
        : "+f"(c[0]), "+f"(c[1]), "+f"(c[2]), "+f"(c[3])
        : "r"(a[0]), "r"(a[1]), "r"(a[2]), "r"(a[3]), "r"(b0), "r"(b1));
}

// ---------------------------------------------------------------------------
// Split fp32 -> bf16 hi + bf16 mid. n divisible by 1024.
// ---------------------------------------------------------------------------
__global__ void split_kernel(const float* __restrict__ in,
                             __nv_bfloat16* __restrict__ hi,
                             __nv_bfloat16* __restrict__ mid, int n)
{
    int i = blockIdx.x * blockDim.x + threadIdx.x;
    float4 v = reinterpret_cast<const float4*>(in)[i];
    __nv_bfloat162 h01 = __floats2bfloat162_rn(v.x, v.y);
    __nv_bfloat162 h23 = __floats2bfloat162_rn(v.z, v.w);
    float2 f01 = __bfloat1622float2(h01);
    float2 f23 = __bfloat1622float2(h23);
    __nv_bfloat162 m01 = __floats2bfloat162_rn(v.x - f01.x, v.y - f01.y);
    __nv_bfloat162 m23 = __floats2bfloat162_rn(v.z - f23.x, v.w - f23.y);
    reinterpret_cast<__nv_bfloat162*>(hi)[2*i]   = h01;
    reinterpret_cast<__nv_bfloat162*>(hi)[2*i+1] = h23;
    reinterpret_cast<__nv_bfloat162*>(mid)[2*i]   = m01;
    reinterpret_cast<__nv_bfloat162*>(mid)[2*i+1] = m23;
}

// Repack W3 (2*512 x 256) into [W3top | W3bot] (512 x 512) with hi/mid split.
// out[k][j] = W3[k + (j>=256)*512][j&255]
__global__ void repack3_kernel(const float* __restrict__ W3,
                               __nv_bfloat16* __restrict__ hi,
                               __nv_bfloat16* __restrict__ mid)
{
    int idx = blockIdx.x * blockDim.x + threadIdx.x;   // 0 .. 512*512-1
    int k = idx >> 9, j = idx & 511;
    float v = W3[(k + ((j >> 8) << 9)) * 256 + (j & 255)];
    __nv_bfloat16 h = __float2bfloat16(v);
    hi[idx]  = h;
    mid[idx] = __float2bfloat16(v - __bfloat162float(h));
}

// ---------------------------------------------------------------------------
// C = act([A1|A2] @ B + res + bias), bf16x3, cp.async 3-stage pipeline.
// 128 thr / 4 warps, warp tile 64x64, CTA tile 128x128. B row stride ldB.
// Optional residual (hi/mid bf16, row stride ldRes, batch stride sRes).
// ---------------------------------------------------------------------------
__global__ __launch_bounds__(128, 2)
void bgemm_kernel(const __nv_bfloat16* __restrict__ Ah1,
                  const __nv_bfloat16* __restrict__ Am1, int K1,
                  const __nv_bfloat16* __restrict__ Ah2,
                  const __nv_bfloat16* __restrict__ Am2, int K2,
                  const __nv_bfloat16* __restrict__ Bh,
                  const __nv_bfloat16* __restrict__ Bm, int ldB,
                  const float* __restrict__ bias,
                  const __nv_bfloat16* __restrict__ resH,
                  const __nv_bfloat16* __restrict__ resM,
                  int ldRes, long sRes,
                  __nv_bfloat16* __restrict__ outHi,
                  __nv_bfloat16* __restrict__ outMid,
                  int N, long sA, long sB, long sC,
                  int act, const float* __restrict__ alpha)
{
    extern __shared__ __align__(1024) char smem[];
    const uint32_t sb = smem_u32(smem);
    const int K  = K1 + K2;
    const int nc = K >> 5;
    const int bz = blockIdx.z;
    const __nv_bfloat16* Ah1b = Ah1 + (size_t)bz * sA;
    const __nv_bfloat16* Am1b = Am1 + (size_t)bz * sA;
    const __nv_bfloat16* Bhb  = Bh + (size_t)bz * sB;
    const __nv_bfloat16* Bmb  = Bm + (size_t)bz * sB;
    const __nv_bfloat16* rHb  = resH ? resH + (size_t)bz * sRes : nullptr;
    const __nv_bfloat16* rMb  = resM ? resM + (size_t)bz * sRes : nullptr;
    __nv_bfloat16* oHi = outHi + (size_t)bz * sC;
    __nv_bfloat16* oMi = outMid + (size_t)bz * sC;

    const int tid  = threadIdx.x;
    const int wid  = tid >> 5;
    const int lane = tid & 31;
    const int warpM = wid >> 1;
    const int warpN = wid & 1;
    const int lr = lane >> 2, lc = lane & 3;

    const int rowBase = blockIdx.y * 128;
    const int colBase = blockIdx.x * 128;

    const uint32_t aLane = (uint32_t)((lane & 15) * A_STRIDE_B + (lane >> 4) * 16);
    const uint32_t bLane = (uint32_t)((((lane & 7) + ((lane >> 3) & 1) * 8)) * B_STRIDE_B
                                      + ((lane >> 4) & 1) * 16);

    float acc[4][8][4];
#pragma unroll
    for (int mi = 0; mi < 4; mi++)
#pragma unroll
        for (int ni = 0; ni < 8; ni++)
#pragma unroll
            for (int j = 0; j < 4; j++) acc[mi][ni][j] = 0.f;

    auto fetch = [&](int ch) {
        const uint32_t stb = sb + (uint32_t)(ch % NST) * STG_BYTES;
        const int kc = ch << 5;
        const __nv_bfloat16 *Aph, *Apm; int lda, ko;
        if (kc < K1) { Aph = Ah1b; Apm = Am1b; lda = K1; ko = kc; }
        else         { Aph = Ah2;  Apm = Am2;  lda = K2; ko = kc - K1; }
#pragma unroll
        for (int i = 0; i < 4; i++) {
            int f = tid + (i << 7);
            int m = f >> 2, q = f & 3;
            size_t so = (size_t)(rowBase + m) * lda + ko + q * 8;
            uint32_t doff = (uint32_t)(m * A_STRIDE_B + q * 16);
            cpa16(stb + A_HI_S  + doff, Aph + so);
            cpa16(stb + A_MID_S + doff, Apm + so);
        }
#pragma unroll
        for (int i = 0; i < 4; i++) {
            int f = tid + (i << 7);
            int k = f >> 4, q = f & 15;
            size_t so = (size_t)(kc + k) * ldB + colBase + q * 8;
            uint32_t doff = (uint32_t)(k * B_STRIDE_B + q * 16);
            cpa16(stb + B_HI_S  + doff, Bhb + so);
            cpa16(stb + B_MID_S + doff, Bmb + so);
        }
    };

    fetch(0); CPA_COMMIT();
    fetch(1); CPA_COMMIT();

    for (int ch = 0; ch < nc; ++ch) {
        CPA_WAIT1();
        __syncthreads();

        if (ch + 2 < nc) fetch(ch + 2);
        CPA_COMMIT();

        const uint32_t stb = sb + (uint32_t)(ch % NST) * STG_BYTES;
        const uint32_t aHiB = stb + A_HI_S  + (uint32_t)(warpM * 64) * A_STRIDE_B + aLane;
        const uint32_t aMiB = stb + A_MID_S + (uint32_t)(warpM * 64) * A_STRIDE_B + aLane;
        const uint32_t bHiB = stb + B_HI_S  + (uint32_t)(warpN * 128) + bLane;
        const uint32_t bMiB = stb + B_MID_S + (uint32_t)(warpN * 128) + bLane;

#pragma unroll
        for (int ks = 0; ks < 2; ks++) {
            uint32_t ah[4][4], am[4][4];
#pragma unroll
            for (int mi = 0; mi < 4; mi++) {
                ldsm_x4(ah[mi], aHiB + mi * 16 * A_STRIDE_B + ks * 32);
                ldsm_x4(am[mi], aMiB + mi * 16 * A_STRIDE_B + ks * 32);
            }
#pragma unroll
            for (int g = 0; g < 4; g++) {
                uint32_t bh[4], bm[4];
                ldsm_x4_trans(bh, bHiB + ks * 16 * B_STRIDE_B + g * 32);
                ldsm_x4_trans(bm, bMiB + ks * 16 * B_STRIDE_B + g * 32);
#pragma unroll
                for (int sub = 0; sub < 2; sub++) {
                    const uint32_t b0h = bh[sub * 2], b1h = bh[sub * 2 + 1];
                    const uint32_t b0m = bm[sub * 2], b1m = bm[sub * 2 + 1];
                    const int ni = g * 2 + sub;
#pragma unroll
                    for (int mi = 0; mi < 4; mi++) {
                        mma_bf16(acc[mi][ni], ah[mi], b0h, b1h);
                        mma_bf16(acc[mi][ni], am[mi], b0h, b1h);
                        mma_bf16(acc[mi][ni], ah[mi], b0m, b1m);
                    }
                }
            }
        }
    }

    // Epilogue: residual + bias + act, write bf16 hi + mid residual
#pragma unroll
    for (int mi = 0; mi < 4; mi++) {
#pragma unroll
        for (int ni = 0; ni < 8; ni++) {
#pragma unroll
            for (int half = 0; half < 2; half++) {
                int r = rowBase + warpM * 64 + mi * 16 + lr + half * 8;
                int c = colBase + warpN * 64 + ni * 8 + lc * 2;
                float v0 = acc[mi][ni][half * 2 + 0];
                float v1 = acc[mi][ni][half * 2 + 1];
                if (rHb) {
                    size_t ro = (size_t)r * ldRes + c;
                    __nv_bfloat162 rh = *reinterpret_cast<const __nv_bfloat162*>(rHb + ro);
                    __nv_bfloat162 rm = *reinterpret_cast<const __nv_bfloat162*>(rMb + ro);
                    float2 fh = __bfloat1622float2(rh);
                    float2 fm = __bfloat1622float2(rm);
                    v0 += fh.x + fm.x;
                    v1 += fh.y + fm.y;
                }
                if (bias) { v0 += bias[c]; v1 += bias[c + 1]; }
                if (act == 1) {
                    v0 = fmaxf(v0, 0.f); v1 = fmaxf(v1, 0.f);
                } else if (act == 2) {
                    v0 = v0 > 0.f ? v0 : alpha[c] * v0;
                    v1 = v1 > 0.f ? v1 : alpha[c + 1] * v1;
                }
                __nv_bfloat162 h2 = __floats2bfloat162_rn(v0, v1);
                float2 hf = __bfloat1622float2(h2);
                __nv_bfloat162 m2 = __floats2bfloat162_rn(v0 - hf.x, v1 - hf.y);
                size_t o = (size_t)r * N + c;
                *reinterpret_cast<__nv_bfloat162*>(oHi + o) = h2;
                *reinterpret_cast<__nv_bfloat162*>(oMi + o) = m2;
            }
        }
    }
}

// pred[M,2] = H[M,K] @ W[K,2] + b[2]; H given as bf16 hi+mid (warp per row)
__global__ void final_head_kernel(const __nv_bfloat16* __restrict__ Hh,
                                  const __nv_bfloat16* __restrict__ Hm,
                                  const float* __restrict__ W,
                                  const float* __restrict__ b,
                                  float* __restrict__ out,
                                  int M, int K)
{
    __shared__ float w0[256], w1[256];
    const int tid = threadIdx.x;
    for (int i = tid; i < K; i += blockDim.x) {
        w0[i] = W[i * 2 + 0];
        w1[i] = W[i * 2 + 1];
    }
    __syncthreads();

    const int warp = tid >> 5;
    const int lane = tid & 31;
    const int row  = blockIdx.x * (blockDim.x >> 5) + warp;
    if (row >= M) return;

    const __nv_bfloat16* hh = Hh + (size_t)row * K;
    const __nv_bfloat16* hm = Hm + (size_t)row * K;
    float s0 = 0.f, s1 = 0.f;
    for (int c = lane; c < K; c += 32) {
        float v = __bfloat162float(hh[c]) + __bfloat162float(hm[c]);
        s0 += v * w0[c];
        s1 += v * w1[c];
    }
#pragma unroll
    for (int o = 16; o; o >>= 1) {
        s0 += __shfl_xor_sync(0xFFFFFFFFu, s0, o);
        s1 += __shfl_xor_sync(0xFFFFFFFFu, s1, o);
    }
    if (lane == 0) {
        out[row * 2 + 0] = s0 + b[0];
        out[row * 2 + 1] = s1 + b[1];
    }
}

extern "C" void kernel_launch(void* const* d_in, const int* in_sizes, int n_in,
                              void* d_out, int out_size)
{
    const float* x   = (const float*)d_in[0];
    const float* adj = (const float*)d_in[1];
    const float* W1  = (const float*)d_in[2];
    const float* b1  = (const float*)d_in[3];
    const float* W2  = (const float*)d_in[4];
    const float* b2  = (const float*)d_in[5];
    const float* W3  = (const float*)d_in[6];
    const float* b3  = (const float*)d_in[7];
    const float* W4  = (const float*)d_in[8];
    const float* b4  = (const float*)d_in[9];
    const float* cW1 = (const float*)d_in[10];
    const float* cb1 = (const float*)d_in[11];
    const float* alp = (const float*)d_in[12];
    const float* cW2 = (const float*)d_in[13];
    const float* cb2 = (const float*)d_in[14];
    float* out = (float*)d_out;

    __nv_bfloat16 *adjH, *adjM, *xH, *xM, *hAH, *hAM, *hBH, *hBM, *agH, *agM, *wH, *wM;
    cudaGetSymbolAddress((void**)&adjH, s_adj_h); cudaGetSymbolAddress((void**)&adjM, s_adj_m);
    cudaGetSymbolAddress((void**)&xH,   s_x_h);   cudaGetSymbolAddress((void**)&xM,   s_x_m);
    cudaGetSymbolAddress((void**)&hAH,  s_hA_h);  cudaGetSymbolAddress((void**)&hAM,  s_hA_m);
    cudaGetSymbolAddress((void**)&hBH,  s_hB_h);  cudaGetSymbolAddress((void**)&hBM,  s_hB_m);
    cudaGetSymbolAddress((void**)&agH,  s_ag_h);  cudaGetSymbolAddress((void**)&agM,  s_ag_m);
    cudaGetSymbolAddress((void**)&wH,   s_w_h);   cudaGetSymbolAddress((void**)&wM,   s_w_m);

    static bool attrSet = false;
    if (!attrSet) {
        cudaFuncSetAttribute(bgemm_kernel, cudaFuncAttributeMaxDynamicSharedMemorySize,
                             SMEM_BYTES);
        attrSet = true;
    }

    const int Bb = 32, Nn = 1024, D = 256, Hd = 512, Hh = 256;
    const int MB = Bb * Nn;  // 32768

    auto split = [&](const float* src, __nv_bfloat16* hi, __nv_bfloat16* mid, int n) {
        split_kernel<<<n / 1024, 256>>>(src, hi, mid, n);
    };

    // Weight offsets inside wH/wM
    const size_t oW1 = 0, oW2 = 262144, oW4 = 786432, oC1 = 917504, oW3r = 1048576;

    split(adj, adjH, adjM, Bb * Nn * Nn);
    split(x,   xH,   xM,   Bb * Nn * D);
    split(W1,  wH + oW1, wM + oW1, 2 * D * Hd);
    split(W2,  wH + oW2, wM + oW2, 2 * Hd * Hd);
    split(W4,  wH + oW4, wM + oW4, 2 * Hh * Hh);
    split(cW1, wH + oC1, wM + oC1, Hh * Hh);
    repack3_kernel<<<(Hd * Hd) / 256, 256>>>(W3, wH + oW3r, wM + oW3r);

    auto gemm = [&](const __nv_bfloat16* Ah1, const __nv_bfloat16* Am1, int K1,
                    const __nv_bfloat16* Ah2, const __nv_bfloat16* Am2, int K2,
                    const __nv_bfloat16* Bh, const __nv_bfloat16* Bm, int ldB,
                    const float* bias,
                    const __nv_bfloat16* rH, const __nv_bfloat16* rM, int ldRes, long sRes,
                    __nv_bfloat16* oH, __nv_bfloat16* oM,
                    int M, int N, int batch, long sA, long sB, long sC,
                    int act, const float* alpha) {
        dim3 g(N / 128, M / 128, batch);
        bgemm_kernel<<<g, 128, SMEM_BYTES>>>(Ah1, Am1, K1, Ah2, Am2, K2, Bh, Bm, ldB,
                                             bias, rH, rM, ldRes, sRes,
                                             oH, oM, N, sA, sB, sC, act, alpha);
    };

    // ---- Layer 1: agg = adj @ x ; h1 = relu([x|agg] W1 + b1) -> hA ----
    gemm(adjH, adjM, Nn, nullptr, nullptr, 0, xH, xM, D, nullptr,
         nullptr, nullptr, 0, 0, agH, agM,
         Nn, D, Bb, (long)Nn * Nn, (long)Nn * D, (long)Nn * D, 0, nullptr);
    gemm(xH, xM, D, agH, agM, D, wH + oW1, wM + oW1, Hd, b1,
         nullptr, nullptr, 0, 0, hAH, hAM,
         MB, Hd, 1, 0, 0, 0, 1, nullptr);

    // ---- Layer 2: agg = adj @ hA ; h2 = relu([hA|agg] W2 + b2) -> hB ----
    gemm(adjH, adjM, Nn, nullptr, nullptr, 0, hAH, hAM, Hd, nullptr,
         nullptr, nullptr, 0, 0, agH, agM,
         Nn, Hd, Bb, (long)Nn * Nn, (long)Nn * Hd, (long)Nn * Hd, 0, nullptr);
    gemm(hAH, hAM, Hd, agH, agM, Hd, wH + oW2, wM + oW2, Hd, b2,
         nullptr, nullptr, 0, 0, hBH, hBM,
         MB, Hd, 1, 0, 0, 0, 1, nullptr);

    // ---- Layer 3 (projection-first): P = hB @ [W3top|W3bot] -> ag (MB x 512)
    //      h3 = relu(adj @ Pbot + Ptop + b3) -> hA (MB x 256) ----
    gemm(hBH, hBM, Hd, nullptr, nullptr, 0, wH + oW3r, wM + oW3r, Hd, nullptr,
         nullptr, nullptr, 0, 0, agH, agM,
         MB, Hd, 1, 0, 0, 0, 0, nullptr);
    gemm(adjH, adjM, Nn, nullptr, nullptr, 0, agH + Hh, agM + Hh, Hd, b3,
         agH, agM, Hd, (long)Nn * Hd, hAH, hAM,
         Nn, Hh, Bb, (long)Nn * Nn, (long)Nn * Hd, (long)Nn * Hh, 1, nullptr);

    // ---- Layer 4: agg = adj @ hA ; h4 = relu([hA|agg] W4 + b4) -> hB ----
    gemm(adjH, adjM, Nn, nullptr, nullptr, 0, hAH, hAM, Hh, nullptr,
         nullptr, nullptr, 0, 0, agH, agM,
         Nn, Hh, Bb, (long)Nn * Nn, (long)Nn * Hh, (long)Nn * Hh, 0, nullptr);
    gemm(hAH, hAM, Hh, agH, agM, Hh, wH + oW4, wM + oW4, Hh, b4,
         nullptr, nullptr, 0, 0, hBH, hBM,
         MB, Hh, 1, 0, 0, 0, 1, nullptr);

    // ---- Classifier: c1 = prelu(hB @ cW1 + cb1) -> hA ; pred -> out ----
    gemm(hBH, hBM, Hh, nullptr, nullptr, 0, wH + oC1, wM + oC1, Hh, cb1,
         nullptr, nullptr, 0, 0, hAH, hAM,
         MB, Hh, 1, 0, 0, 0, 2, alp);
    final_head_kernel<<<MB / 8, 256>>>(hAH, hAM, cW2, cb2, out, MB, Hh);
}

// round 15
// speedup vs baseline: 2.9405x; 1.0013x over previous
#include <cuda_runtime.h>
#include <cuda_bf16.h>
#include <cstdint>
#include <cstddef>

// ---------------- bf16 scratch (no allocs allowed) ----------------
__device__ __nv_bfloat16 s_adj_h[32u*1024u*1024u];
__device__ __nv_bfloat16 s_adj_m[32u*1024u*1024u];
__device__ __nv_bfloat16 s_x_h[32u*1024u*256u];
__device__ __nv_bfloat16 s_x_m[32u*1024u*256u];
__device__ __nv_bfloat16 s_hA_h[32u*1024u*512u];
__device__ __nv_bfloat16 s_hA_m[32u*1024u*512u];
__device__ __nv_bfloat16 s_hB_h[32u*1024u*512u];
__device__ __nv_bfloat16 s_hB_m[32u*1024u*512u];
__device__ __nv_bfloat16 s_ag_h[32u*1024u*512u];
__device__ __nv_bfloat16 s_ag_m[32u*1024u*512u];
__device__ __nv_bfloat16 s_w_h[2u<<20];
__device__ __nv_bfloat16 s_w_m[2u<<20];

// ---------------- smem geometry (bytes) ----------------
#define A_STRIDE_B 80
#define B_STRIDE_B 272
#define A_HI_S  0
#define A_MID_S 10240
#define B_HI_S  20480
#define B_MID_S 29184
#define STG_BYTES 37888
#define NST 3
#define SMEM_BYTES (NST * STG_BYTES)   // 113664

__device__ __forceinline__ uint32_t smem_u32(const void* p) {
    uint32_t a;
    asm("{ .reg .u64 t; cvta.to.shared.u64 t, %1; cvt.u32.u64 %0, t; }" : "=r"(a) : "l"(p));
    return a;
}
__device__ __forceinline__ void cpa16(uint32_t dst, const void* src) {
    asm volatile("cp.async.cg.shared.global [%0], [%1], 16;" :: "r"(dst), "l"(src));
}
#define CPA_COMMIT() asm volatile("cp.async.commit_group;" ::: "memory")
#define CPA_WAIT1()  asm volatile("cp.async.wait_group 1;" ::: "memory")

__device__ __forceinline__ void ldsm_x4(uint32_t r[4], uint32_t addr) {
    asm volatile("ldmatrix.sync.aligned.m8n8.x4.shared.b16 {%0,%1,%2,%3}, [%4];"
                 : "=r"(r[0]), "=r"(r[1]), "=r"(r[2]), "=r"(r[3]) : "r"(addr));
}
__device__ __forceinline__ void ldsm_x4_trans(uint32_t r[4], uint32_t addr) {
    asm volatile("ldmatrix.sync.aligned.m8n8.x4.trans.shared.b16 {%0,%1,%2,%3}, [%4];"
                 : "=r"(r[0]), "=r"(r[1]), "=r"(r[2]), "=r"(r[3]) : "r"(addr));
}
__device__ __forceinline__ void mma_bf16(float c[4], const uint32_t a[4],
                                         uint32_t b0, uint32_t b1) {
    asm volatile(
        "mma.sync.aligned.m16n8k16.row.col.f32.bf16.bf16.f32 "
        "{%0,%1,%2,%3}, {%4,%5,%6,%7}, {%8,%9}, {%0,%1,%2,%3};"
        : "+f"(c[0]), "+f"(c[1]), "+f"(c[2]), "+f"(c[3])
        : "r"(a[0]), "r"(a[1]), "r"(a[2]), "r"(a[3]), "r"(b0), "r"(b1));
}

// ---------------------------------------------------------------------------
// Split fp32 -> bf16 hi + bf16 mid. n divisible by 1024.
// ---------------------------------------------------------------------------
__global__ void split_kernel(const float* __restrict__ in,
                             __nv_bfloat16* __restrict__ hi,
                             __nv_bfloat16* __restrict__ mid, int n)
{
    int i = blockIdx.x * blockDim.x + threadIdx.x;
    float4 v = reinterpret_cast<const float4*>(in)[i];
    __nv_bfloat162 h01 = __floats2bfloat162_rn(v.x, v.y);
    __nv_bfloat162 h23 = __floats2bfloat162_rn(v.z, v.w);
    float2 f01 = __bfloat1622float2(h01);
    float2 f23 = __bfloat1622float2(h23);
    __nv_bfloat162 m01 = __floats2bfloat162_rn(v.x - f01.x, v.y - f01.y);
    __nv_bfloat162 m23 = __floats2bfloat162_rn(v.z - f23.x, v.w - f23.y);
    reinterpret_cast<__nv_bfloat162*>(hi)[2*i]   = h01;
    reinterpret_cast<__nv_bfloat162*>(hi)[2*i+1] = h23;
    reinterpret_cast<__nv_bfloat162*>(mid)[2*i]   = m01;
    reinterpret_cast<__nv_bfloat162*>(mid)[2*i+1] = m23;
}

// Fused split for W1, W2, W4, cW1 into wH/wM at fixed element offsets.
// float4 ranges: W1 65536 | W2 131072 | W4 32768 | cW1 16384  (total 245760)
__global__ void split_w_kernel(const float* __restrict__ W1,
                               const float* __restrict__ W2,
                               const float* __restrict__ W4,
                               const float* __restrict__ cW1,
                               __nv_bfloat16* __restrict__ wH,
                               __nv_bfloat16* __restrict__ wM)
{
    int i = blockIdx.x * blockDim.x + threadIdx.x;
    int j; const float* s; size_t off;
    if (i < 65536)       { j = i;          s = W1;  off = 0; }
    else if (i < 196608) { j = i - 65536;  s = W2;  off = 262144; }
    else if (i < 229376) { j = i - 196608; s = W4;  off = 786432; }
    else                 { j = i - 229376; s = cW1; off = 917504; }
    float4 v = reinterpret_cast<const float4*>(s)[j];
    __nv_bfloat162 h01 = __floats2bfloat162_rn(v.x, v.y);
    __nv_bfloat162 h23 = __floats2bfloat162_rn(v.z, v.w);
    float2 f01 = __bfloat1622float2(h01);
    float2 f23 = __bfloat1622float2(h23);
    __nv_bfloat162 m01 = __floats2bfloat162_rn(v.x - f01.x, v.y - f01.y);
    __nv_bfloat162 m23 = __floats2bfloat162_rn(v.z - f23.x, v.w - f23.y);
    reinterpret_cast<__nv_bfloat162*>(wH + off)[2*j]   = h01;
    reinterpret_cast<__nv_bfloat162*>(wH + off)[2*j+1] = h23;
    reinterpret_cast<__nv_bfloat162*>(wM + off)[2*j]   = m01;
    reinterpret_cast<__nv_bfloat162*>(wM + off)[2*j+1] = m23;
}

// Repack W3 (2*512 x 256) into [W3top | W3bot] (512 x 512) with hi/mid split.
__global__ void repack3_kernel(const float* __restrict__ W3,
                               __nv_bfloat16* __restrict__ hi,
                               __nv_bfloat16* __restrict__ mid)
{
    int idx = blockIdx.x * blockDim.x + threadIdx.x;   // 0 .. 512*512-1
    int k = idx >> 9, j = idx & 511;
    float v = W3[(k + ((j >> 8) << 9)) * 256 + (j & 255)];
    __nv_bfloat16 h = __float2bfloat16(v);
    hi[idx]  = h;
    mid[idx] = __float2bfloat16(v - __bfloat162float(h));
}

// ---------------------------------------------------------------------------
// C = act([A1|A2] @ B + res + bias), bf16x3, cp.async 3-stage pipeline,
// software-pipelined fragment loads. 128 thr / 4 warps, warp tile 64x64.
// ---------------------------------------------------------------------------
__global__ __launch_bounds__(128, 2)
void bgemm_kernel(const __nv_bfloat16* __restrict__ Ah1,
                  const __nv_bfloat16* __restrict__ Am1, int K1,
                  const __nv_bfloat16* __restrict__ Ah2,
                  const __nv_bfloat16* __restrict__ Am2, int K2,
                  const __nv_bfloat16* __restrict__ Bh,
                  const __nv_bfloat16* __restrict__ Bm, int ldB,
                  const float* __restrict__ bias,
                  const __nv_bfloat16* __restrict__ resH,
                  const __nv_bfloat16* __restrict__ resM,
                  int ldRes, long sRes,
                  __nv_bfloat16* __restrict__ outHi,
                  __nv_bfloat16* __restrict__ outMid,
                  int N, long sA, long sB, long sC,
                  int act, const float* __restrict__ alpha)
{
    extern __shared__ __align__(1024) char smem[];
    const uint32_t sb = smem_u32(smem);
    const int K  = K1 + K2;
    const int nc = K >> 5;
    const int bz = blockIdx.z;
    const __nv_bfloat16* Ah1b = Ah1 + (size_t)bz * sA;
    const __nv_bfloat16* Am1b = Am1 + (size_t)bz * sA;
    const __nv_bfloat16* Bhb  = Bh + (size_t)bz * sB;
    const __nv_bfloat16* Bmb  = Bm + (size_t)bz * sB;
    const __nv_bfloat16* rHb  = resH ? resH + (size_t)bz * sRes : nullptr;
    const __nv_bfloat16* rMb  = resM ? resM + (size_t)bz * sRes : nullptr;
    __nv_bfloat16* oHi = outHi + (size_t)bz * sC;
    __nv_bfloat16* oMi = outMid + (size_t)bz * sC;

    const int tid  = threadIdx.x;
    const int wid  = tid >> 5;
    const int lane = tid & 31;
    const int warpM = wid >> 1;
    const int warpN = wid & 1;
    const int lr = lane >> 2, lc = lane & 3;

    const int rowBase = blockIdx.y * 128;
    const int colBase = blockIdx.x * 128;

    const uint32_t aLane = (uint32_t)((lane & 15) * A_STRIDE_B + (lane >> 4) * 16);
    const uint32_t bLane = (uint32_t)((((lane & 7) + ((lane >> 3) & 1) * 8)) * B_STRIDE_B
                                      + ((lane >> 4) & 1) * 16);

    float acc[4][8][4];
#pragma unroll
    for (int mi = 0; mi < 4; mi++)
#pragma unroll
        for (int ni = 0; ni < 8; ni++)
#pragma unroll
            for (int j = 0; j < 4; j++) acc[mi][ni][j] = 0.f;

    auto fetch = [&](int ch) {
        const uint32_t stb = sb + (uint32_t)(ch % NST) * STG_BYTES;
        const int kc = ch << 5;
        const __nv_bfloat16 *Aph, *Apm; int lda, ko;
        if (kc < K1) { Aph = Ah1b; Apm = Am1b; lda = K1; ko = kc; }
        else         { Aph = Ah2;  Apm = Am2;  lda = K2; ko = kc - K1; }
#pragma unroll
        for (int i = 0; i < 4; i++) {
            int f = tid + (i << 7);
            int m = f >> 2, q = f & 3;
            size_t so = (size_t)(rowBase + m) * lda + ko + q * 8;
            uint32_t doff = (uint32_t)(m * A_STRIDE_B + q * 16);
            cpa16(stb + A_HI_S  + doff, Aph + so);
            cpa16(stb + A_MID_S + doff, Apm + so);
        }
#pragma unroll
        for (int i = 0; i < 4; i++) {
            int f = tid + (i << 7);
            int k = f >> 4, q = f & 15;
            size_t so = (size_t)(kc + k) * ldB + colBase + q * 8;
            uint32_t doff = (uint32_t)(k * B_STRIDE_B + q * 16);
            cpa16(stb + B_HI_S  + doff, Bhb + so);
            cpa16(stb + B_MID_S + doff, Bmb + so);
        }
    };

    fetch(0); CPA_COMMIT();
    fetch(1); CPA_COMMIT();

    for (int ch = 0; ch < nc; ++ch) {
        CPA_WAIT1();
        __syncthreads();

        if (ch + 2 < nc) fetch(ch + 2);
        CPA_COMMIT();

        const uint32_t stb = sb + (uint32_t)(ch % NST) * STG_BYTES;
        const uint32_t aHiB = stb + A_HI_S  + (uint32_t)(warpM * 64) * A_STRIDE_B + aLane;
        const uint32_t aMiB = stb + A_MID_S + (uint32_t)(warpM * 64) * A_STRIDE_B + aLane;
        const uint32_t bHiB = stb + B_HI_S  + (uint32_t)(warpN * 128) + bLane;
        const uint32_t bMiB = stb + B_MID_S + (uint32_t)(warpN * 128) + bLane;

        // Load ALL A fragments for this chunk up front (latency hidden by MMAs)
        uint32_t ah[2][4][4], am[2][4][4];
#pragma unroll
        for (int ks = 0; ks < 2; ks++)
#pragma unroll
            for (int mi = 0; mi < 4; mi++) {
                ldsm_x4(ah[ks][mi], aHiB + mi * 16 * A_STRIDE_B + ks * 32);
                ldsm_x4(am[ks][mi], aMiB + mi * 16 * A_STRIDE_B + ks * 32);
            }

        // Double-buffered B group pipeline: 8 groups (ks 0..1 x g 0..3)
        uint32_t bh[2][4], bm[2][4];
        ldsm_x4_trans(bh[0], bHiB);
        ldsm_x4_trans(bm[0], bMiB);
#pragma unroll
        for (int G = 0; G < 8; G++) {
            const int cur = G & 1;
            if (G < 7) {
                const int Gn = G + 1;
                const uint32_t off = (uint32_t)((Gn >> 2) * 16 * B_STRIDE_B + (Gn & 3) * 32);
                ldsm_x4_trans(bh[cur ^ 1], bHiB + off);
                ldsm_x4_trans(bm[cur ^ 1], bMiB + off);
            }
            const int ks = G >> 2, g = G & 3;
#pragma unroll
            for (int sub = 0; sub < 2; sub++) {
                const uint32_t b0h = bh[cur][sub * 2], b1h = bh[cur][sub * 2 + 1];
                const uint32_t b0m = bm[cur][sub * 2], b1m = bm[cur][sub * 2 + 1];
                const int ni = g * 2 + sub;
#pragma unroll
                for (int mi = 0; mi < 4; mi++) {
                    mma_bf16(acc[mi][ni], ah[ks][mi], b0h, b1h);
                    mma_bf16(acc[mi][ni], am[ks][mi], b0h, b1h);
                    mma_bf16(acc[mi][ni], ah[ks][mi], b0m, b1m);
                }
            }
        }
    }

    // Epilogue: residual + bias + act, write bf16 hi + mid residual
#pragma unroll
    for (int mi = 0; mi < 4; mi++) {
#pragma unroll
        for (int ni = 0; ni < 8; ni++) {
#pragma unroll
            for (int half = 0; half < 2; half++) {
                int r = rowBase + warpM * 64 + mi * 16 + lr + half * 8;
                int c = colBase + warpN * 64 + ni * 8 + lc * 2;
                float v0 = acc[mi][ni][half * 2 + 0];
                float v1 = acc[mi][ni][half * 2 + 1];
                if (rHb) {
                    size_t ro = (size_t)r * ldRes + c;
                    __nv_bfloat162 rh = *reinterpret_cast<const __nv_bfloat162*>(rHb + ro);
                    __nv_bfloat162 rm = *reinterpret_cast<const __nv_bfloat162*>(rMb + ro);
                    float2 fh = __bfloat1622float2(rh);
                    float2 fm = __bfloat1622float2(rm);
                    v0 += fh.x + fm.x;
                    v1 += fh.y + fm.y;
                }
                if (bias) { v0 += bias[c]; v1 += bias[c + 1]; }
                if (act == 1) {
                    v0 = fmaxf(v0, 0.f); v1 = fmaxf(v1, 0.f);
                } else if (act == 2) {
                    v0 = v0 > 0.f ? v0 : alpha[c] * v0;
                    v1 = v1 > 0.f ? v1 : alpha[c + 1] * v1;
                }
                __nv_bfloat162 h2 = __floats2bfloat162_rn(v0, v1);
                float2 hf = __bfloat1622float2(h2);
                __nv_bfloat162 m2 = __floats2bfloat162_rn(v0 - hf.x, v1 - hf.y);
                size_t o = (size_t)r * N + c;
                *reinterpret_cast<__nv_bfloat162*>(oHi + o) = h2;
                *reinterpret_cast<__nv_bfloat162*>(oMi + o) = m2;
            }
        }
    }
}

// pred[M,2] = H[M,K] @ W[K,2] + b[2]; H given as bf16 hi+mid (warp per row)
__global__ void final_head_kernel(const __nv_bfloat16* __restrict__ Hh,
                                  const __nv_bfloat16* __restrict__ Hm,
                                  const float* __restrict__ W,
                                  const float* __restrict__ b,
                                  float* __restrict__ out,
                                  int M, int K)
{
    __shared__ float w0[256], w1[256];
    const int tid = threadIdx.x;
    for (int i = tid; i < K; i += blockDim.x) {
        w0[i] = W[i * 2 + 0];
        w1[i] = W[i * 2 + 1];
    }
    __syncthreads();

    const int warp = tid >> 5;
    const int lane = tid & 31;
    const int row  = blockIdx.x * (blockDim.x >> 5) + warp;
    if (row >= M) return;

    const __nv_bfloat16* hh = Hh + (size_t)row * K;
    const __nv_bfloat16* hm = Hm + (size_t)row * K;
    float s0 = 0.f, s1 = 0.f;
    for (int c = lane; c < K; c += 32) {
        float v = __bfloat162float(hh[c]) + __bfloat162float(hm[c]);
        s0 += v * w0[c];
        s1 += v * w1[c];
    }
#pragma unroll
    for (int o = 16; o; o >>= 1) {
        s0 += __shfl_xor_sync(0xFFFFFFFFu, s0, o);
        s1 += __shfl_xor_sync(0xFFFFFFFFu, s1, o);
    }
    if (lane == 0) {
        out[row * 2 + 0] = s0 + b[0];
        out[row * 2 + 1] = s1 + b[1];
    }
}

extern "C" void kernel_launch(void* const* d_in, const int* in_sizes, int n_in,
                              void* d_out, int out_size)
{
    const float* x   = (const float*)d_in[0];
    const float* adj = (const float*)d_in[1];
    const float* W1  = (const float*)d_in[2];
    const float* b1  = (const float*)d_in[3];
    const float* W2  = (const float*)d_in[4];
    const float* b2  = (const float*)d_in[5];
    const float* W3  = (const float*)d_in[6];
    const float* b3  = (const float*)d_in[7];
    const float* W4  = (const float*)d_in[8];
    const float* b4  = (const float*)d_in[9];
    const float* cW1 = (const float*)d_in[10];
    const float* cb1 = (const float*)d_in[11];
    const float* alp = (const float*)d_in[12];
    const float* cW2 = (const float*)d_in[13];
    const float* cb2 = (const float*)d_in[14];
    float* out = (float*)d_out;

    __nv_bfloat16 *adjH, *adjM, *xH, *xM, *hAH, *hAM, *hBH, *hBM, *agH, *agM, *wH, *wM;
    cudaGetSymbolAddress((void**)&adjH, s_adj_h); cudaGetSymbolAddress((void**)&adjM, s_adj_m);
    cudaGetSymbolAddress((void**)&xH,   s_x_h);   cudaGetSymbolAddress((void**)&xM,   s_x_m);
    cudaGetSymbolAddress((void**)&hAH,  s_hA_h);  cudaGetSymbolAddress((void**)&hAM,  s_hA_m);
    cudaGetSymbolAddress((void**)&hBH,  s_hB_h);  cudaGetSymbolAddress((void**)&hBM,  s_hB_m);
    cudaGetSymbolAddress((void**)&agH,  s_ag_h);  cudaGetSymbolAddress((void**)&agM,  s_ag_m);
    cudaGetSymbolAddress((void**)&wH,   s_w_h);   cudaGetSymbolAddress((void**)&wM,   s_w_m);

    static bool attrSet = false;
    if (!attrSet) {
        cudaFuncSetAttribute(bgemm_kernel, cudaFuncAttributeMaxDynamicSharedMemorySize,
                             SMEM_BYTES);
        attrSet = true;
    }

    const int Bb = 32, Nn = 1024, D = 256, Hd = 512, Hh = 256;
    const int MB = Bb * Nn;  // 32768

    // Weight element offsets inside wH/wM
    const size_t oW1 = 0, oW2 = 262144, oW4 = 786432, oC1 = 917504, oW3r = 1048576;

    split_kernel<<<(Bb * Nn * Nn) / 1024, 256>>>(adj, adjH, adjM, Bb * Nn * Nn);
    split_kernel<<<(Bb * Nn * D) / 1024, 256>>>(x, xH, xM, Bb * Nn * D);
    split_w_kernel<<<960, 256>>>(W1, W2, W4, cW1, wH, wM);
    repack3_kernel<<<(Hd * Hd) / 256, 256>>>(W3, wH + oW3r, wM + oW3r);

    auto gemm = [&](const __nv_bfloat16* Ah1, const __nv_bfloat16* Am1, int K1,
                    const __nv_bfloat16* Ah2, const __nv_bfloat16* Am2, int K2,
                    const __nv_bfloat16* Bh, const __nv_bfloat16* Bm, int ldB,
                    const float* bias,
                    const __nv_bfloat16* rH, const __nv_bfloat16* rM, int ldRes, long sRes,
                    __nv_bfloat16* oH, __nv_bfloat16* oM,
                    int M, int N, int batch, long sA, long sB, long sC,
                    int act, const float* alpha) {
        dim3 g(N / 128, M / 128, batch);
        bgemm_kernel<<<g, 128, SMEM_BYTES>>>(Ah1, Am1, K1, Ah2, Am2, K2, Bh, Bm, ldB,
                                             bias, rH, rM, ldRes, sRes,
                                             oH, oM, N, sA, sB, sC, act, alpha);
    };

    // ---- Layer 1: agg = adj @ x ; h1 = relu([x|agg] W1 + b1) -> hA ----
    gemm(adjH, adjM, Nn, nullptr, nullptr, 0, xH, xM, D, nullptr,
         nullptr, nullptr, 0, 0, agH, agM,
         Nn, D, Bb, (long)Nn * Nn, (long)Nn * D, (long)Nn * D, 0, nullptr);
    gemm(xH, xM, D, agH, agM, D, wH + oW1, wM + oW1, Hd, b1,
         nullptr, nullptr, 0, 0, hAH, hAM,
         MB, Hd, 1, 0, 0, 0, 1, nullptr);

    // ---- Layer 2: agg = adj @ hA ; h2 = relu([hA|agg] W2 + b2) -> hB ----
    gemm(adjH, adjM, Nn, nullptr, nullptr, 0, hAH, hAM, Hd, nullptr,
         nullptr, nullptr, 0, 0, agH, agM,
         Nn, Hd, Bb, (long)Nn * Nn, (long)Nn * Hd, (long)Nn * Hd, 0, nullptr);
    gemm(hAH, hAM, Hd, agH, agM, Hd, wH + oW2, wM + oW2, Hd, b2,
         nullptr, nullptr, 0, 0, hBH, hBM,
         MB, Hd, 1, 0, 0, 0, 1, nullptr);

    // ---- Layer 3 (projection-first): P = hB @ [W3top|W3bot] -> ag (MB x 512)
    //      h3 = relu(adj @ Pbot + Ptop + b3) -> hA (MB x 256) ----
    gemm(hBH, hBM, Hd, nullptr, nullptr, 0, wH + oW3r, wM + oW3r, Hd, nullptr,
         nullptr, nullptr, 0, 0, agH, agM,
         MB, Hd, 1, 0, 0, 0, 0, nullptr);
    gemm(adjH, adjM, Nn, nullptr, nullptr, 0, agH + Hh, agM + Hh, Hd, b3,
         agH, agM, Hd, (long)Nn * Hd, hAH, hAM,
         Nn, Hh, Bb, (long)Nn * Nn, (long)Nn * Hd, (long)Nn * Hh, 1, nullptr);

    // ---- Layer 4: agg = adj @ hA ; h4 = relu([hA|agg] W4 + b4) -> hB ----
    gemm(adjH, adjM, Nn, nullptr, nullptr, 0, hAH, hAM, Hh, nullptr,
         nullptr, nullptr, 0, 0, agH, agM,
         Nn, Hh, Bb, (long)Nn * Nn, (long)Nn * Hh, (long)Nn * Hh, 0, nullptr);
    gemm(hAH, hAM, Hh, agH, agM, Hh, wH + oW4, wM + oW4, Hh, b4,
         nullptr, nullptr, 0, 0, hBH, hBM,
         MB, Hh, 1, 0, 0, 0, 1, nullptr);

    // ---- Classifier: c1 = prelu(hB @ cW1 + cb1) -> hA ; pred -> out ----
    gemm(hBH, hBM, Hh, nullptr, nullptr, 0, wH + oC1, wM + oC1, Hh, cb1,
         nullptr, nullptr, 0, 0, hAH, hAM,
         MB, Hh, 1, 0, 0, 0, 2, alp);
    final_head_kernel<<<MB / 8, 256>>>(hAH, hAM, cW2, cb2, out, MB, Hh);
}

// round 16
// speedup vs baseline: 3.8951x; 1.3246x over previous
#include <cuda_runtime.h>
#include <cuda_fp16.h>
#include <cstdint>
#include <cstddef>

// ---------------- fp16 scratch (no allocs allowed) ----------------
__device__ __half s_adj_h[32u*1024u*1024u];
__device__ __half s_adj_m[32u*1024u*1024u];
__device__ __half s_x_h[32u*1024u*256u];
__device__ __half s_x_m[32u*1024u*256u];
__device__ __half s_hA_h[32u*1024u*512u];
__device__ __half s_hA_m[32u*1024u*512u];
__device__ __half s_hB_h[32u*1024u*512u];
__device__ __half s_hB_m[32u*1024u*512u];
__device__ __half s_ag_h[32u*1024u*512u];
__device__ __half s_ag_m[32u*1024u*512u];
__device__ __half s_w_h[2u<<20];
__device__ __half s_w_m[2u<<20];

// ---------------- smem geometry (bytes) ----------------
// A: [128 m][32 k] fp16 hi+mid, row stride 80B. B: [32 k][128 n] fp16 hi only.
#define A_STRIDE_B 80
#define B_STRIDE_B 272
#define A_HI_S  0
#define A_MID_S 10240
#define B_HI_S  20480
#define STG_BYTES 29184
#define NST 3
#define SMEM_BYTES (NST * STG_BYTES)   // 87552

__device__ __forceinline__ uint32_t smem_u32(const void* p) {
    uint32_t a;
    asm("{ .reg .u64 t; cvta.to.shared.u64 t, %1; cvt.u32.u64 %0, t; }" : "=r"(a) : "l"(p));
    return a;
}
__device__ __forceinline__ void cpa16(uint32_t dst, const void* src) {
    asm volatile("cp.async.cg.shared.global [%0], [%1], 16;" :: "r"(dst), "l"(src));
}
#define CPA_COMMIT() asm volatile("cp.async.commit_group;" ::: "memory")
#define CPA_WAIT1()  asm volatile("cp.async.wait_group 1;" ::: "memory")

__device__ __forceinline__ void ldsm_x4(uint32_t r[4], uint32_t addr) {
    asm volatile("ldmatrix.sync.aligned.m8n8.x4.shared.b16 {%0,%1,%2,%3}, [%4];"
                 : "=r"(r[0]), "=r"(r[1]), "=r"(r[2]), "=r"(r[3]) : "r"(addr));
}
__device__ __forceinline__ void ldsm_x4_trans(uint32_t r[4], uint32_t addr) {
    asm volatile("ldmatrix.sync.aligned.m8n8.x4.trans.shared.b16 {%0,%1,%2,%3}, [%4];"
                 : "=r"(r[0]), "=r"(r[1]), "=r"(r[2]), "=r"(r[3]) : "r"(addr));
}
__device__ __forceinline__ void mma_f16(float c[4], const uint32_t a[4],
                                        uint32_t b0, uint32_t b1) {
    asm volatile(
        "mma.sync.aligned.m16n8k16.row.col.f32.f16.f16.f32 "
        "{%0,%1,%2,%3}, {%4,%5,%6,%7}, {%8,%9}, {%0,%1,%2,%3};"
        : "+f"(c[0]), "+f"(c[1]), "+f"(c[2]), "+f"(c[3])
        : "r"(a[0]), "r"(a[1]), "r"(a[2]), "r"(a[3]), "r"(b0), "r"(b1));
}

// ---------------------------------------------------------------------------
// Split fp32 -> fp16 hi + fp16 mid (residual). n divisible by 1024.
// ---------------------------------------------------------------------------
__global__ void split_kernel(const float* __restrict__ in,
                             __half* __restrict__ hi,
                             __half* __restrict__ mid, int n)
{
    int i = blockIdx.x * blockDim.x + threadIdx.x;
    float4 v = reinterpret_cast<const float4*>(in)[i];
    __half2 h01 = __floats2half2_rn(v.x, v.y);
    __half2 h23 = __floats2half2_rn(v.z, v.w);
    float2 f01 = __half22float2(h01);
    float2 f23 = __half22float2(h23);
    __half2 m01 = __floats2half2_rn(v.x - f01.x, v.y - f01.y);
    __half2 m23 = __floats2half2_rn(v.z - f23.x, v.w - f23.y);
    reinterpret_cast<__half2*>(hi)[2*i]   = h01;
    reinterpret_cast<__half2*>(hi)[2*i+1] = h23;
    reinterpret_cast<__half2*>(mid)[2*i]   = m01;
    reinterpret_cast<__half2*>(mid)[2*i+1] = m23;
}

// Fused split for W1, W2, W4, cW1 into wH/wM at fixed element offsets.
// float4 ranges: W1 65536 | W2 131072 | W4 32768 | cW1 16384  (total 245760)
__global__ void split_w_kernel(const float* __restrict__ W1,
                               const float* __restrict__ W2,
                               const float* __restrict__ W4,
                               const float* __restrict__ cW1,
                               __half* __restrict__ wH,
                               __half* __restrict__ wM)
{
    int i = blockIdx.x * blockDim.x + threadIdx.x;
    int j; const float* s; size_t off;
    if (i < 65536)       { j = i;          s = W1;  off = 0; }
    else if (i < 196608) { j = i - 65536;  s = W2;  off = 262144; }
    else if (i < 229376) { j = i - 196608; s = W4;  off = 786432; }
    else                 { j = i - 229376; s = cW1; off = 917504; }
    float4 v = reinterpret_cast<const float4*>(s)[j];
    __half2 h01 = __floats2half2_rn(v.x, v.y);
    __half2 h23 = __floats2half2_rn(v.z, v.w);
    float2 f01 = __half22float2(h01);
    float2 f23 = __half22float2(h23);
    __half2 m01 = __floats2half2_rn(v.x - f01.x, v.y - f01.y);
    __half2 m23 = __floats2half2_rn(v.z - f23.x, v.w - f23.y);
    reinterpret_cast<__half2*>(wH + off)[2*j]   = h01;
    reinterpret_cast<__half2*>(wH + off)[2*j+1] = h23;
    reinterpret_cast<__half2*>(wM + off)[2*j]   = m01;
    reinterpret_cast<__half2*>(wM + off)[2*j+1] = m23;
}

// Repack W3 (2*512 x 256) into [W3top | W3bot] (512 x 512), fp16 hi/mid.
__global__ void repack3_kernel(const float* __restrict__ W3,
                               __half* __restrict__ hi,
                               __half* __restrict__ mid)
{
    int idx = blockIdx.x * blockDim.x + threadIdx.x;   // 0 .. 512*512-1
    int k = idx >> 9, j = idx & 511;
    float v = W3[(k + ((j >> 8) << 9)) * 256 + (j & 255)];
    __half h = __float2half_rn(v);
    hi[idx]  = h;
    mid[idx] = __float2half_rn(v - __half2float(h));
}

// ---------------------------------------------------------------------------
// C = act([A1|A2] @ B + res + bias), fp16 2-term (Ah*Bh + Am*Bh),
// cp.async 3-stage pipeline. 128 thr / 4 warps, warp tile 64x64.
// A is hi/mid fp16 pair; B hi-only fp16. Optional residual (hi/mid fp16).
// ---------------------------------------------------------------------------
__global__ __launch_bounds__(128, 2)
void bgemm_kernel(const __half* __restrict__ Ah1,
                  const __half* __restrict__ Am1, int K1,
                  const __half* __restrict__ Ah2,
                  const __half* __restrict__ Am2, int K2,
                  const __half* __restrict__ Bh, int ldB,
                  const float* __restrict__ bias,
                  const __half* __restrict__ resH,
                  const __half* __restrict__ resM,
                  int ldRes, long sRes,
                  __half* __restrict__ outHi,
                  __half* __restrict__ outMid,
                  int N, long sA, long sB, long sC,
                  int act, const float* __restrict__ alpha)
{
    extern __shared__ __align__(1024) char smem[];
    const uint32_t sb = smem_u32(smem);
    const int K  = K1 + K2;
    const int nc = K >> 5;
    const int bz = blockIdx.z;
    const __half* Ah1b = Ah1 + (size_t)bz * sA;
    const __half* Am1b = Am1 + (size_t)bz * sA;
    const __half* Bhb  = Bh + (size_t)bz * sB;
    const __half* rHb  = resH ? resH + (size_t)bz * sRes : nullptr;
    const __half* rMb  = resM ? resM + (size_t)bz * sRes : nullptr;
    __half* oHi = outHi + (size_t)bz * sC;
    __half* oMi = outMid + (size_t)bz * sC;

    const int tid  = threadIdx.x;
    const int wid  = tid >> 5;
    const int lane = tid & 31;
    const int warpM = wid >> 1;
    const int warpN = wid & 1;
    const int lr = lane >> 2, lc = lane & 3;

    const int rowBase = blockIdx.y * 128;
    const int colBase = blockIdx.x * 128;

    const uint32_t aLane = (uint32_t)((lane & 15) * A_STRIDE_B + (lane >> 4) * 16);
    const uint32_t bLane = (uint32_t)((((lane & 7) + ((lane >> 3) & 1) * 8)) * B_STRIDE_B
                                      + ((lane >> 4) & 1) * 16);

    float acc[4][8][4];
#pragma unroll
    for (int mi = 0; mi < 4; mi++)
#pragma unroll
        for (int ni = 0; ni < 8; ni++)
#pragma unroll
            for (int j = 0; j < 4; j++) acc[mi][ni][j] = 0.f;

    auto fetch = [&](int ch) {
        const uint32_t stb = sb + (uint32_t)(ch % NST) * STG_BYTES;
        const int kc = ch << 5;
        const __half *Aph, *Apm; int lda, ko;
        if (kc < K1) { Aph = Ah1b; Apm = Am1b; lda = K1; ko = kc; }
        else         { Aph = Ah2;  Apm = Am2;  lda = K2; ko = kc - K1; }
#pragma unroll
        for (int i = 0; i < 4; i++) {
            int f = tid + (i << 7);
            int m = f >> 2, q = f & 3;
            size_t so = (size_t)(rowBase + m) * lda + ko + q * 8;
            uint32_t doff = (uint32_t)(m * A_STRIDE_B + q * 16);
            cpa16(stb + A_HI_S  + doff, Aph + so);
            cpa16(stb + A_MID_S + doff, Apm + so);
        }
#pragma unroll
        for (int i = 0; i < 4; i++) {
            int f = tid + (i << 7);
            int k = f >> 4, q = f & 15;
            size_t so = (size_t)(kc + k) * ldB + colBase + q * 8;
            uint32_t doff = (uint32_t)(k * B_STRIDE_B + q * 16);
            cpa16(stb + B_HI_S + doff, Bhb + so);
        }
    };

    fetch(0); CPA_COMMIT();
    fetch(1); CPA_COMMIT();

    for (int ch = 0; ch < nc; ++ch) {
        CPA_WAIT1();
        __syncthreads();

        if (ch + 2 < nc) fetch(ch + 2);
        CPA_COMMIT();

        const uint32_t stb = sb + (uint32_t)(ch % NST) * STG_BYTES;
        const uint32_t aHiB = stb + A_HI_S  + (uint32_t)(warpM * 64) * A_STRIDE_B + aLane;
        const uint32_t aMiB = stb + A_MID_S + (uint32_t)(warpM * 64) * A_STRIDE_B + aLane;
        const uint32_t bHiB = stb + B_HI_S  + (uint32_t)(warpN * 128) + bLane;

        // Load all A fragments for this chunk up front
        uint32_t ah[2][4][4], am[2][4][4];
#pragma unroll
        for (int ks = 0; ks < 2; ks++)
#pragma unroll
            for (int mi = 0; mi < 4; mi++) {
                ldsm_x4(ah[ks][mi], aHiB + mi * 16 * A_STRIDE_B + ks * 32);
                ldsm_x4(am[ks][mi], aMiB + mi * 16 * A_STRIDE_B + ks * 32);
            }

        // Double-buffered B group pipeline: 8 groups (ks 0..1 x g 0..3)
        uint32_t bh[2][4];
        ldsm_x4_trans(bh[0], bHiB);
#pragma unroll
        for (int G = 0; G < 8; G++) {
            const int cur = G & 1;
            if (G < 7) {
                const int Gn = G + 1;
                const uint32_t off = (uint32_t)((Gn >> 2) * 16 * B_STRIDE_B + (Gn & 3) * 32);
                ldsm_x4_trans(bh[cur ^ 1], bHiB + off);
            }
            const int ks = G >> 2, g = G & 3;
#pragma unroll
            for (int sub = 0; sub < 2; sub++) {
                const uint32_t b0 = bh[cur][sub * 2], b1 = bh[cur][sub * 2 + 1];
                const int ni = g * 2 + sub;
#pragma unroll
                for (int mi = 0; mi < 4; mi++) {
                    mma_f16(acc[mi][ni], ah[ks][mi], b0, b1);
                    mma_f16(acc[mi][ni], am[ks][mi], b0, b1);
                }
            }
        }
    }

    // Epilogue: residual + bias + act, write fp16 hi + mid residual
#pragma unroll
    for (int mi = 0; mi < 4; mi++) {
#pragma unroll
        for (int ni = 0; ni < 8; ni++) {
#pragma unroll
            for (int half_ = 0; half_ < 2; half_++) {
                int r = rowBase + warpM * 64 + mi * 16 + lr + half_ * 8;
                int c = colBase + warpN * 64 + ni * 8 + lc * 2;
                float v0 = acc[mi][ni][half_ * 2 + 0];
                float v1 = acc[mi][ni][half_ * 2 + 1];
                if (rHb) {
                    size_t ro = (size_t)r * ldRes + c;
                    __half2 rh = *reinterpret_cast<const __half2*>(rHb + ro);
                    __half2 rm = *reinterpret_cast<const __half2*>(rMb + ro);
                    float2 fh = __half22float2(rh);
                    float2 fm = __half22float2(rm);
                    v0 += fh.x + fm.x;
                    v1 += fh.y + fm.y;
                }
                if (bias) { v0 += bias[c]; v1 += bias[c + 1]; }
                if (act == 1) {
                    v0 = fmaxf(v0, 0.f); v1 = fmaxf(v1, 0.f);
                } else if (act == 2) {
                    v0 = v0 > 0.f ? v0 : alpha[c] * v0;
                    v1 = v1 > 0.f ? v1 : alpha[c + 1] * v1;
                }
                __half2 h2 = __floats2half2_rn(v0, v1);
                float2 hf = __half22float2(h2);
                __half2 m2 = __floats2half2_rn(v0 - hf.x, v1 - hf.y);
                size_t o = (size_t)r * N + c;
                *reinterpret_cast<__half2*>(oHi + o) = h2;
                *reinterpret_cast<__half2*>(oMi + o) = m2;
            }
        }
    }
}

// pred[M,2] = H[M,K] @ W[K,2] + b[2]; H given as fp16 hi+mid (warp per row)
__global__ void final_head_kernel(const __half* __restrict__ Hh,
                                  const __half* __restrict__ Hm,
                                  const float* __restrict__ W,
                                  const float* __restrict__ b,
                                  float* __restrict__ out,
                                  int M, int K)
{
    __shared__ float w0[256], w1[256];
    const int tid = threadIdx.x;
    for (int i = tid; i < K; i += blockDim.x) {
        w0[i] = W[i * 2 + 0];
        w1[i] = W[i * 2 + 1];
    }
    __syncthreads();

    const int warp = tid >> 5;
    const int lane = tid & 31;
    const int row  = blockIdx.x * (blockDim.x >> 5) + warp;
    if (row >= M) return;

    const __half* hh = Hh + (size_t)row * K;
    const __half* hm = Hm + (size_t)row * K;
    float s0 = 0.f, s1 = 0.f;
    for (int c = lane; c < K; c += 32) {
        float v = __half2float(hh[c]) + __half2float(hm[c]);
        s0 += v * w0[c];
        s1 += v * w1[c];
    }
#pragma unroll
    for (int o = 16; o; o >>= 1) {
        s0 += __shfl_xor_sync(0xFFFFFFFFu, s0, o);
        s1 += __shfl_xor_sync(0xFFFFFFFFu, s1, o);
    }
    if (lane == 0) {
        out[row * 2 + 0] = s0 + b[0];
        out[row * 2 + 1] = s1 + b[1];
    }
}

extern "C" void kernel_launch(void* const* d_in, const int* in_sizes, int n_in,
                              void* d_out, int out_size)
{
    const float* x   = (const float*)d_in[0];
    const float* adj = (const float*)d_in[1];
    const float* W1  = (const float*)d_in[2];
    const float* b1  = (const float*)d_in[3];
    const float* W2  = (const float*)d_in[4];
    const float* b2  = (const float*)d_in[5];
    const float* W3  = (const float*)d_in[6];
    const float* b3  = (const float*)d_in[7];
    const float* W4  = (const float*)d_in[8];
    const float* b4  = (const float*)d_in[9];
    const float* cW1 = (const float*)d_in[10];
    const float* cb1 = (const float*)d_in[11];
    const float* alp = (const float*)d_in[12];
    const float* cW2 = (const float*)d_in[13];
    const float* cb2 = (const float*)d_in[14];
    float* out = (float*)d_out;

    __half *adjH, *adjM, *xH, *xM, *hAH, *hAM, *hBH, *hBM, *agH, *agM, *wH, *wM;
    cudaGetSymbolAddress((void**)&adjH, s_adj_h); cudaGetSymbolAddress((void**)&adjM, s_adj_m);
    cudaGetSymbolAddress((void**)&xH,   s_x_h);   cudaGetSymbolAddress((void**)&xM,   s_x_m);
    cudaGetSymbolAddress((void**)&hAH,  s_hA_h);  cudaGetSymbolAddress((void**)&hAM,  s_hA_m);
    cudaGetSymbolAddress((void**)&hBH,  s_hB_h);  cudaGetSymbolAddress((void**)&hBM,  s_hB_m);
    cudaGetSymbolAddress((void**)&agH,  s_ag_h);  cudaGetSymbolAddress((void**)&agM,  s_ag_m);
    cudaGetSymbolAddress((void**)&wH,   s_w_h);   cudaGetSymbolAddress((void**)&wM,   s_w_m);

    static bool attrSet = false;
    if (!attrSet) {
        cudaFuncSetAttribute(bgemm_kernel, cudaFuncAttributeMaxDynamicSharedMemorySize,
                             SMEM_BYTES);
        attrSet = true;
    }

    const int Bb = 32, Nn = 1024, D = 256, Hd = 512, Hh = 256;
    const int MB = Bb * Nn;  // 32768

    // Weight element offsets inside wH/wM
    const size_t oW1 = 0, oW2 = 262144, oW4 = 786432, oC1 = 917504, oW3r = 1048576;

    split_kernel<<<(Bb * Nn * Nn) / 1024, 256>>>(adj, adjH, adjM, Bb * Nn * Nn);
    split_kernel<<<(Bb * Nn * D) / 1024, 256>>>(x, xH, xM, Bb * Nn * D);
    split_w_kernel<<<960, 256>>>(W1, W2, W4, cW1, wH, wM);
    repack3_kernel<<<(Hd * Hd) / 256, 256>>>(W3, wH + oW3r, wM + oW3r);

    auto gemm = [&](const __half* Ah1, const __half* Am1, int K1,
                    const __half* Ah2, const __half* Am2, int K2,
                    const __half* Bh, int ldB,
                    const float* bias,
                    const __half* rH, const __half* rM, int ldRes, long sRes,
                    __half* oH, __half* oM,
                    int M, int N, int batch, long sA, long sB, long sC,
                    int act, const float* alpha) {
        dim3 g(N / 128, M / 128, batch);
        bgemm_kernel<<<g, 128, SMEM_BYTES>>>(Ah1, Am1, K1, Ah2, Am2, K2, Bh, ldB,
                                             bias, rH, rM, ldRes, sRes,
                                             oH, oM, N, sA, sB, sC, act, alpha);
    };

    // ---- Layer 1: agg = adj @ x ; h1 = relu([x|agg] W1 + b1) -> hA ----
    gemm(adjH, adjM, Nn, nullptr, nullptr, 0, xH, D, nullptr,
         nullptr, nullptr, 0, 0, agH, agM,
         Nn, D, Bb, (long)Nn * Nn, (long)Nn * D, (long)Nn * D, 0, nullptr);
    gemm(xH, xM, D, agH, agM, D, wH + oW1, Hd, b1,
         nullptr, nullptr, 0, 0, hAH, hAM,
         MB, Hd, 1, 0, 0, 0, 1, nullptr);

    // ---- Layer 2: agg = adj @ hA ; h2 = relu([hA|agg] W2 + b2) -> hB ----
    gemm(adjH, adjM, Nn, nullptr, nullptr, 0, hAH, Hd, nullptr,
         nullptr, nullptr, 0, 0, agH, agM,
         Nn, Hd, Bb, (long)Nn * Nn, (long)Nn * Hd, (long)Nn * Hd, 0, nullptr);
    gemm(hAH, hAM, Hd, agH, agM, Hd, wH + oW2, Hd, b2,
         nullptr, nullptr, 0, 0, hBH, hBM,
         MB, Hd, 1, 0, 0, 0, 1, nullptr);

    // ---- Layer 3 (projection-first): P = hB @ [W3top|W3bot] -> ag (MB x 512)
    //      h3 = relu(adj @ Pbot + Ptop + b3) -> hA (MB x 256) ----
    gemm(hBH, hBM, Hd, nullptr, nullptr, 0, wH + oW3r, Hd, nullptr,
         nullptr, nullptr, 0, 0, agH, agM,
         MB, Hd, 1, 0, 0, 0, 0, nullptr);
    gemm(adjH, adjM, Nn, nullptr, nullptr, 0, agH + Hh, Hd, b3,
         agH, agM, Hd, (long)Nn * Hd, hAH, hAM,
         Nn, Hh, Bb, (long)Nn * Nn, (long)Nn * Hd, (long)Nn * Hh, 1, nullptr);

    // ---- Layer 4: agg = adj @ hA ; h4 = relu([hA|agg] W4 + b4) -> hB ----
    gemm(adjH, adjM, Nn, nullptr, nullptr, 0, hAH, Hh, nullptr,
         nullptr, nullptr, 0, 0, agH, agM,
         Nn, Hh, Bb, (long)Nn * Nn, (long)Nn * Hh, (long)Nn * Hh, 0, nullptr);
    gemm(hAH, hAM, Hh, agH, agM, Hh, wH + oW4, Hh, b4,
         nullptr, nullptr, 0, 0, hBH, hBM,
         MB, Hh, 1, 0, 0, 0, 1, nullptr);

    // ---- Classifier: c1 = prelu(hB @ cW1 + cb1) -> hA ; pred -> out ----
    gemm(hBH, hBM, Hh, nullptr, nullptr, 0, wH + oC1, Hh, cb1,
         nullptr, nullptr, 0, 0, hAH, hAM,
         MB, Hh, 1, 0, 0, 0, 2, alp);
    final_head_kernel<<<MB / 8, 256>>>(hAH, hAM, cW2, cb2, out, MB, Hh);
}

// round 17
// speedup vs baseline: 3.9217x; 1.0068x over previous
#include <cuda_runtime.h>
#include <cuda_fp16.h>
#include <cstdint>
#include <cstddef>

// ---------------- fp16 scratch (no allocs allowed) ----------------
__device__ __half s_adj_h[32u*1024u*1024u];
__device__ __half s_adj_m[32u*1024u*1024u];
__device__ __half s_x_h[32u*1024u*256u];
__device__ __half s_x_m[32u*1024u*256u];
__device__ __half s_hA_h[32u*1024u*512u];
__device__ __half s_hA_m[32u*1024u*512u];
__device__ __half s_hB_h[32u*1024u*512u];
__device__ __half s_hB_m[32u*1024u*512u];
__device__ __half s_ag_h[32u*1024u*512u];
__device__ __half s_ag_m[32u*1024u*512u];
__device__ __half s_w_h[2u<<20];
__device__ __half s_w_m[2u<<20];

// ---------------- smem geometry (bytes) ----------------
// A: [128 m][32 k] fp16 hi+mid, row stride 80B. B: [32 k][128 n] fp16 hi only.
#define A_STRIDE_B 80
#define B_STRIDE_B 272
#define A_HI_S  0
#define A_MID_S 10240
#define B_HI_S  20480
#define STG_BYTES 29184
#define NST 3
#define SMEM_BYTES (NST * STG_BYTES)   // 87552

__device__ __forceinline__ uint32_t smem_u32(const void* p) {
    uint32_t a;
    asm("{ .reg .u64 t; cvta.to.shared.u64 t, %1; cvt.u32.u64 %0, t; }" : "=r"(a) : "l"(p));
    return a;
}
__device__ __forceinline__ void cpa16(uint32_t dst, const void* src) {
    asm volatile("cp.async.cg.shared.global [%0], [%1], 16;" :: "r"(dst), "l"(src));
}
#define CPA_COMMIT() asm volatile("cp.async.commit_group;" ::: "memory")
#define CPA_WAIT1()  asm volatile("cp.async.wait_group 1;" ::: "memory")

__device__ __forceinline__ void ldsm_x4(uint32_t r[4], uint32_t addr) {
    asm volatile("ldmatrix.sync.aligned.m8n8.x4.shared.b16 {%0,%1,%2,%3}, [%4];"
                 : "=r"(r[0]), "=r"(r[1]), "=r"(r[2]), "=r"(r[3]) : "r"(addr));
}
__device__ __forceinline__ void ldsm_x4_trans(uint32_t r[4], uint32_t addr) {
    asm volatile("ldmatrix.sync.aligned.m8n8.x4.trans.shared.b16 {%0,%1,%2,%3}, [%4];"
                 : "=r"(r[0]), "=r"(r[1]), "=r"(r[2]), "=r"(r[3]) : "r"(addr));
}
__device__ __forceinline__ void mma_f16(float c[4], const uint32_t a[4],
                                        uint32_t b0, uint32_t b1) {
    asm volatile(
        "mma.sync.aligned.m16n8k16.row.col.f32.f16.f16.f32 "
        "{%0,%1,%2,%3}, {%4,%5,%6,%7}, {%8,%9}, {%0,%1,%2,%3};"
        : "+f"(c[0]), "+f"(c[1]), "+f"(c[2]), "+f"(c[3])
        : "r"(a[0]), "r"(a[1]), "r"(a[2]), "r"(a[3]), "r"(b0), "r"(b1));
}

// ---------------------------------------------------------------------------
// Split fp32 -> fp16 hi + fp16 mid (residual). n divisible by 1024.
// ---------------------------------------------------------------------------
__global__ void split_kernel(const float* __restrict__ in,
                             __half* __restrict__ hi,
                             __half* __restrict__ mid, int n)
{
    int i = blockIdx.x * blockDim.x + threadIdx.x;
    float4 v = reinterpret_cast<const float4*>(in)[i];
    __half2 h01 = __floats2half2_rn(v.x, v.y);
    __half2 h23 = __floats2half2_rn(v.z, v.w);
    float2 f01 = __half22float2(h01);
    float2 f23 = __half22float2(h23);
    __half2 m01 = __floats2half2_rn(v.x - f01.x, v.y - f01.y);
    __half2 m23 = __floats2half2_rn(v.z - f23.x, v.w - f23.y);
    reinterpret_cast<__half2*>(hi)[2*i]   = h01;
    reinterpret_cast<__half2*>(hi)[2*i+1] = h23;
    reinterpret_cast<__half2*>(mid)[2*i]   = m01;
    reinterpret_cast<__half2*>(mid)[2*i+1] = m23;
}

// Fused split for W1, W2, W4, cW1 into wH/wM at fixed element offsets.
__global__ void split_w_kernel(const float* __restrict__ W1,
                               const float* __restrict__ W2,
                               const float* __restrict__ W4,
                               const float* __restrict__ cW1,
                               __half* __restrict__ wH,
                               __half* __restrict__ wM)
{
    int i = blockIdx.x * blockDim.x + threadIdx.x;
    int j; const float* s; size_t off;
    if (i < 65536)       { j = i;          s = W1;  off = 0; }
    else if (i < 196608) { j = i - 65536;  s = W2;  off = 262144; }
    else if (i < 229376) { j = i - 196608; s = W4;  off = 786432; }
    else                 { j = i - 229376; s = cW1; off = 917504; }
    float4 v = reinterpret_cast<const float4*>(s)[j];
    __half2 h01 = __floats2half2_rn(v.x, v.y);
    __half2 h23 = __floats2half2_rn(v.z, v.w);
    float2 f01 = __half22float2(h01);
    float2 f23 = __half22float2(h23);
    __half2 m01 = __floats2half2_rn(v.x - f01.x, v.y - f01.y);
    __half2 m23 = __floats2half2_rn(v.z - f23.x, v.w - f23.y);
    reinterpret_cast<__half2*>(wH + off)[2*j]   = h01;
    reinterpret_cast<__half2*>(wH + off)[2*j+1] = h23;
    reinterpret_cast<__half2*>(wM + off)[2*j]   = m01;
    reinterpret_cast<__half2*>(wM + off)[2*j+1] = m23;
}

// Repack W3 (2*512 x 256) into [W3top | W3bot] (512 x 512), fp16 hi/mid.
__global__ void repack3_kernel(const float* __restrict__ W3,
                               __half* __restrict__ hi,
                               __half* __restrict__ mid)
{
    int idx = blockIdx.x * blockDim.x + threadIdx.x;   // 0 .. 512*512-1
    int k = idx >> 9, j = idx & 511;
    float v = W3[(k + ((j >> 8) << 9)) * 256 + (j & 255)];
    __half h = __float2half_rn(v);
    hi[idx]  = h;
    mid[idx] = __float2half_rn(v - __half2float(h));
}

// Initialize out[M,2] with the head bias (also clears 0xAA poison).
__global__ void init_out_kernel(float* __restrict__ out, const float* __restrict__ b)
{
    int i = blockIdx.x * blockDim.x + threadIdx.x;
    out[i] = b[i & 1];
}

// ---------------------------------------------------------------------------
// C = act([A1|A2] @ B + res + bias), fp16 2-term (Ah*Bh + Am*Bh),
// cp.async 3-stage pipeline. 128 thr / 4 warps, warp tile 64x64.
// act: 0 none, 1 relu, 2 prelu, 3 prelu + fused head (atomicAdd into headOut).
// ---------------------------------------------------------------------------
__global__ __launch_bounds__(128, 2)
void bgemm_kernel(const __half* __restrict__ Ah1,
                  const __half* __restrict__ Am1, int K1,
                  const __half* __restrict__ Ah2,
                  const __half* __restrict__ Am2, int K2,
                  const __half* __restrict__ Bh, int ldB,
                  const float* __restrict__ bias,
                  const __half* __restrict__ resH,
                  const __half* __restrict__ resM,
                  int ldRes, long sRes,
                  __half* __restrict__ outHi,
                  __half* __restrict__ outMid,
                  int N, long sA, long sB, long sC,
                  int act, const float* __restrict__ alpha,
                  const float* __restrict__ headW,
                  float* __restrict__ headOut)
{
    extern __shared__ __align__(1024) char smem[];
    const uint32_t sb = smem_u32(smem);
    const int K  = K1 + K2;
    const int nc = K >> 5;
    const int bz = blockIdx.z;
    const __half* Ah1b = Ah1 + (size_t)bz * sA;
    const __half* Am1b = Am1 + (size_t)bz * sA;
    const __half* Bhb  = Bh + (size_t)bz * sB;
    const __half* rHb  = resH ? resH + (size_t)bz * sRes : nullptr;
    const __half* rMb  = resM ? resM + (size_t)bz * sRes : nullptr;
    __half* oHi = outHi ? outHi + (size_t)bz * sC : nullptr;
    __half* oMi = outMid ? outMid + (size_t)bz * sC : nullptr;

    const int tid  = threadIdx.x;
    const int wid  = tid >> 5;
    const int lane = tid & 31;
    const int warpM = wid >> 1;
    const int warpN = wid & 1;
    const int lr = lane >> 2, lc = lane & 3;

    const int rowBase = blockIdx.y * 128;
    const int colBase = blockIdx.x * 128;

    const uint32_t aLane = (uint32_t)((lane & 15) * A_STRIDE_B + (lane >> 4) * 16);
    const uint32_t bLane = (uint32_t)((((lane & 7) + ((lane >> 3) & 1) * 8)) * B_STRIDE_B
                                      + ((lane >> 4) & 1) * 16);

    float acc[4][8][4];
#pragma unroll
    for (int mi = 0; mi < 4; mi++)
#pragma unroll
        for (int ni = 0; ni < 8; ni++)
#pragma unroll
            for (int j = 0; j < 4; j++) acc[mi][ni][j] = 0.f;

    auto fetch = [&](int ch) {
        const uint32_t stb = sb + (uint32_t)(ch % NST) * STG_BYTES;
        const int kc = ch << 5;
        const __half *Aph, *Apm; int lda, ko;
        if (kc < K1) { Aph = Ah1b; Apm = Am1b; lda = K1; ko = kc; }
        else         { Aph = Ah2;  Apm = Am2;  lda = K2; ko = kc - K1; }
#pragma unroll
        for (int i = 0; i < 4; i++) {
            int f = tid + (i << 7);
            int m = f >> 2, q = f & 3;
            size_t so = (size_t)(rowBase + m) * lda + ko + q * 8;
            uint32_t doff = (uint32_t)(m * A_STRIDE_B + q * 16);
            cpa16(stb + A_HI_S  + doff, Aph + so);
            cpa16(stb + A_MID_S + doff, Apm + so);
        }
#pragma unroll
        for (int i = 0; i < 4; i++) {
            int f = tid + (i << 7);
            int k = f >> 4, q = f & 15;
            size_t so = (size_t)(kc + k) * ldB + colBase + q * 8;
            uint32_t doff = (uint32_t)(k * B_STRIDE_B + q * 16);
            cpa16(stb + B_HI_S + doff, Bhb + so);
        }
    };

    fetch(0); CPA_COMMIT();
    fetch(1); CPA_COMMIT();

    for (int ch = 0; ch < nc; ++ch) {
        CPA_WAIT1();
        __syncthreads();

        if (ch + 2 < nc) fetch(ch + 2);
        CPA_COMMIT();

        const uint32_t stb = sb + (uint32_t)(ch % NST) * STG_BYTES;
        const uint32_t aHiB = stb + A_HI_S  + (uint32_t)(warpM * 64) * A_STRIDE_B + aLane;
        const uint32_t aMiB = stb + A_MID_S + (uint32_t)(warpM * 64) * A_STRIDE_B + aLane;
        const uint32_t bHiB = stb + B_HI_S  + (uint32_t)(warpN * 128) + bLane;

        // Load all A fragments for this chunk up front
        uint32_t ah[2][4][4], am[2][4][4];
#pragma unroll
        for (int ks = 0; ks < 2; ks++)
#pragma unroll
            for (int mi = 0; mi < 4; mi++) {
                ldsm_x4(ah[ks][mi], aHiB + mi * 16 * A_STRIDE_B + ks * 32);
                ldsm_x4(am[ks][mi], aMiB + mi * 16 * A_STRIDE_B + ks * 32);
            }

        // Double-buffered B group pipeline: 8 groups (ks 0..1 x g 0..3)
        uint32_t bh[2][4];
        ldsm_x4_trans(bh[0], bHiB);
#pragma unroll
        for (int G = 0; G < 8; G++) {
            const int cur = G & 1;
            if (G < 7) {
                const int Gn = G + 1;
                const uint32_t off = (uint32_t)((Gn >> 2) * 16 * B_STRIDE_B + (Gn & 3) * 32);
                ldsm_x4_trans(bh[cur ^ 1], bHiB + off);
            }
            const int ks = G >> 2, g = G & 3;
#pragma unroll
            for (int sub = 0; sub < 2; sub++) {
                const uint32_t b0 = bh[cur][sub * 2], b1 = bh[cur][sub * 2 + 1];
                const int ni = g * 2 + sub;
                // hi terms first (4 independent accs), then mid terms:
                // avoids back-to-back dependent writes to the same acc tile.
#pragma unroll
                for (int mi = 0; mi < 4; mi++)
                    mma_f16(acc[mi][ni], ah[ks][mi], b0, b1);
#pragma unroll
                for (int mi = 0; mi < 4; mi++)
                    mma_f16(acc[mi][ni], am[ks][mi], b0, b1);
            }
        }
    }

    if (act == 3) {
        // Fused classifier epilogue: prelu then partial head dot, atomicAdd.
#pragma unroll
        for (int mi = 0; mi < 4; mi++) {
#pragma unroll
            for (int half_ = 0; half_ < 2; half_++) {
                int r = rowBase + warpM * 64 + mi * 16 + lr + half_ * 8;
                float s0 = 0.f, s1 = 0.f;
#pragma unroll
                for (int ni = 0; ni < 8; ni++) {
                    int c = colBase + warpN * 64 + ni * 8 + lc * 2;
                    float v0 = acc[mi][ni][half_ * 2 + 0] + bias[c];
                    float v1 = acc[mi][ni][half_ * 2 + 1] + bias[c + 1];
                    v0 = v0 > 0.f ? v0 : alpha[c] * v0;
                    v1 = v1 > 0.f ? v1 : alpha[c + 1] * v1;
                    s0 += v0 * headW[2 * c]     + v1 * headW[2 * c + 2];
                    s1 += v0 * headW[2 * c + 1] + v1 * headW[2 * c + 3];
                }
                atomicAdd(headOut + 2 * r,     s0);
                atomicAdd(headOut + 2 * r + 1, s1);
            }
        }
        return;
    }

    // Epilogue: residual + bias + act, write fp16 hi + mid residual
#pragma unroll
    for (int mi = 0; mi < 4; mi++) {
#pragma unroll
        for (int ni = 0; ni < 8; ni++) {
#pragma unroll
            for (int half_ = 0; half_ < 2; half_++) {
                int r = rowBase + warpM * 64 + mi * 16 + lr + half_ * 8;
                int c = colBase + warpN * 64 + ni * 8 + lc * 2;
                float v0 = acc[mi][ni][half_ * 2 + 0];
                float v1 = acc[mi][ni][half_ * 2 + 1];
                if (rHb) {
                    size_t ro = (size_t)r * ldRes + c;
                    __half2 rh = *reinterpret_cast<const __half2*>(rHb + ro);
                    __half2 rm = *reinterpret_cast<const __half2*>(rMb + ro);
                    float2 fh = __half22float2(rh);
                    float2 fm = __half22float2(rm);
                    v0 += fh.x + fm.x;
                    v1 += fh.y + fm.y;
                }
                if (bias) { v0 += bias[c]; v1 += bias[c + 1]; }
                if (act == 1) {
                    v0 = fmaxf(v0, 0.f); v1 = fmaxf(v1, 0.f);
                } else if (act == 2) {
                    v0 = v0 > 0.f ? v0 : alpha[c] * v0;
                    v1 = v1 > 0.f ? v1 : alpha[c + 1] * v1;
                }
                __half2 h2 = __floats2half2_rn(v0, v1);
                float2 hf = __half22float2(h2);
                __half2 m2 = __floats2half2_rn(v0 - hf.x, v1 - hf.y);
                size_t o = (size_t)r * N + c;
                *reinterpret_cast<__half2*>(oHi + o) = h2;
                *reinterpret_cast<__half2*>(oMi + o) = m2;
            }
        }
    }
}

extern "C" void kernel_launch(void* const* d_in, const int* in_sizes, int n_in,
                              void* d_out, int out_size)
{
    const float* x   = (const float*)d_in[0];
    const float* adj = (const float*)d_in[1];
    const float* W1  = (const float*)d_in[2];
    const float* b1  = (const float*)d_in[3];
    const float* W2  = (const float*)d_in[4];
    const float* b2  = (const float*)d_in[5];
    const float* W3  = (const float*)d_in[6];
    const float* b3  = (const float*)d_in[7];
    const float* W4  = (const float*)d_in[8];
    const float* b4  = (const float*)d_in[9];
    const float* cW1 = (const float*)d_in[10];
    const float* cb1 = (const float*)d_in[11];
    const float* alp = (const float*)d_in[12];
    const float* cW2 = (const float*)d_in[13];
    const float* cb2 = (const float*)d_in[14];
    float* out = (float*)d_out;

    __half *adjH, *adjM, *xH, *xM, *hAH, *hAM, *hBH, *hBM, *agH, *agM, *wH, *wM;
    cudaGetSymbolAddress((void**)&adjH, s_adj_h); cudaGetSymbolAddress((void**)&adjM, s_adj_m);
    cudaGetSymbolAddress((void**)&xH,   s_x_h);   cudaGetSymbolAddress((void**)&xM,   s_x_m);
    cudaGetSymbolAddress((void**)&hAH,  s_hA_h);  cudaGetSymbolAddress((void**)&hAM,  s_hA_m);
    cudaGetSymbolAddress((void**)&hBH,  s_hB_h);  cudaGetSymbolAddress((void**)&hBM,  s_hB_m);
    cudaGetSymbolAddress((void**)&agH,  s_ag_h);  cudaGetSymbolAddress((void**)&agM,  s_ag_m);
    cudaGetSymbolAddress((void**)&wH,   s_w_h);   cudaGetSymbolAddress((void**)&wM,   s_w_m);

    static bool attrSet = false;
    if (!attrSet) {
        cudaFuncSetAttribute(bgemm_kernel, cudaFuncAttributeMaxDynamicSharedMemorySize,
                             SMEM_BYTES);
        attrSet = true;
    }

    const int Bb = 32, Nn = 1024, D = 256, Hd = 512, Hh = 256;
    const int MB = Bb * Nn;  // 32768

    // Weight element offsets inside wH/wM
    const size_t oW1 = 0, oW2 = 262144, oW4 = 786432, oC1 = 917504, oW3r = 1048576;

    split_kernel<<<(Bb * Nn * Nn) / 1024, 256>>>(adj, adjH, adjM, Bb * Nn * Nn);
    split_kernel<<<(Bb * Nn * D) / 1024, 256>>>(x, xH, xM, Bb * Nn * D);
    split_w_kernel<<<960, 256>>>(W1, W2, W4, cW1, wH, wM);
    repack3_kernel<<<(Hd * Hd) / 256, 256>>>(W3, wH + oW3r, wM + oW3r);
    init_out_kernel<<<(MB * 2) / 256, 256>>>(out, cb2);

    auto gemm = [&](const __half* Ah1, const __half* Am1, int K1,
                    const __half* Ah2, const __half* Am2, int K2,
                    const __half* Bh, int ldB,
                    const float* bias,
                    const __half* rH, const __half* rM, int ldRes, long sRes,
                    __half* oH, __half* oM,
                    int M, int N, int batch, long sA, long sB, long sC,
                    int act, const float* alpha,
                    const float* headW = nullptr, float* headOut = nullptr) {
        dim3 g(N / 128, M / 128, batch);
        bgemm_kernel<<<g, 128, SMEM_BYTES>>>(Ah1, Am1, K1, Ah2, Am2, K2, Bh, ldB,
                                             bias, rH, rM, ldRes, sRes,
                                             oH, oM, N, sA, sB, sC, act, alpha,
                                             headW, headOut);
    };

    // ---- Layer 1: agg = adj @ x ; h1 = relu([x|agg] W1 + b1) -> hA ----
    gemm(adjH, adjM, Nn, nullptr, nullptr, 0, xH, D, nullptr,
         nullptr, nullptr, 0, 0, agH, agM,
         Nn, D, Bb, (long)Nn * Nn, (long)Nn * D, (long)Nn * D, 0, nullptr);
    gemm(xH, xM, D, agH, agM, D, wH + oW1, Hd, b1,
         nullptr, nullptr, 0, 0, hAH, hAM,
         MB, Hd, 1, 0, 0, 0, 1, nullptr);

    // ---- Layer 2: agg = adj @ hA ; h2 = relu([hA|agg] W2 + b2) -> hB ----
    gemm(adjH, adjM, Nn, nullptr, nullptr, 0, hAH, Hd, nullptr,
         nullptr, nullptr, 0, 0, agH, agM,
         Nn, Hd, Bb, (long)Nn * Nn, (long)Nn * Hd, (long)Nn * Hd, 0, nullptr);
    gemm(hAH, hAM, Hd, agH, agM, Hd, wH + oW2, Hd, b2,
         nullptr, nullptr, 0, 0, hBH, hBM,
         MB, Hd, 1, 0, 0, 0, 1, nullptr);

    // ---- Layer 3 (projection-first): P = hB @ [W3top|W3bot] -> ag (MB x 512)
    //      h3 = relu(adj @ Pbot + Ptop + b3) -> hA (MB x 256) ----
    gemm(hBH, hBM, Hd, nullptr, nullptr, 0, wH + oW3r, Hd, nullptr,
         nullptr, nullptr, 0, 0, agH, agM,
         MB, Hd, 1, 0, 0, 0, 0, nullptr);
    gemm(adjH, adjM, Nn, nullptr, nullptr, 0, agH + Hh, Hd, b3,
         agH, agM, Hd, (long)Nn * Hd, hAH, hAM,
         Nn, Hh, Bb, (long)Nn * Nn, (long)Nn * Hd, (long)Nn * Hh, 1, nullptr);

    // ---- Layer 4: agg = adj @ hA ; h4 = relu([hA|agg] W4 + b4) -> hB ----
    gemm(adjH, adjM, Nn, nullptr, nullptr, 0, hAH, Hh, nullptr,
         nullptr, nullptr, 0, 0, agH, agM,
         Nn, Hh, Bb, (long)Nn * Nn, (long)Nn * Hh, (long)Nn * Hh, 0, nullptr);
    gemm(hAH, hAM, Hh, agH, agM, Hh, wH + oW4, Hh, b4,
         nullptr, nullptr, 0, 0, hBH, hBM,
         MB, Hh, 1, 0, 0, 0, 1, nullptr);

    // ---- Classifier fused with head: out += headW-dot(prelu(hB@cW1+cb1)) ----
    gemm(hBH, hBM, Hh, nullptr, nullptr, 0, wH + oC1, Hh, cb1,
         nullptr, nullptr, 0, 0, nullptr, nullptr,
         MB, Hh, 1, 0, 0, 0, 3, alp, cW2, out);
}